// round 1
// baseline (speedup 1.0000x reference)
#include <cuda_runtime.h>
#include <math.h>
#include <stdint.h>

// Problem constants
#define NB      8
#define LSEQ    4096
#define DMODEL  1024
#define NH      8
#define DKH     128
#define TOPK    16
#define NROWS   (NB * DMODEL)          // 8192 rows of length LSEQ

// ---------------------------------------------------------------------------
// Scratch (device globals; no runtime allocation allowed)
// ---------------------------------------------------------------------------
__device__ float g_qT[(size_t)NROWS * LSEQ];   // [b*1024 + hd][l]
__device__ float g_kT[(size_t)NROWS * LSEQ];
__device__ float g_vT[(size_t)NROWS * LSEQ];
__device__ float g_aT[(size_t)NROWS * LSEQ];

// ---------------------------------------------------------------------------
// SGEMM: C = A @ W + bias   (M=32768, N=1024, K=1024)
// MODE 0: A row-major [M,K]; C written batched-transposed:
//         C[(b*1024 + n)*4096 + l], m = b*4096 + l
// MODE 1: A batched-K-major: A[m,k] = src[(b*1024 + k)*4096 + l]; C row-major [M,N]
// 128x128 tile, k-slab 8, 256 threads, 8x8 per thread.
// grid: x = n-tile (8), y = m-tile (256)  (n fastest -> L2 reuse of A strip)
// ---------------------------------------------------------------------------
template<int MODE>
__global__ void __launch_bounds__(256, 2) sgemm_kernel(
    const float* __restrict__ A, const float* __restrict__ W,
    const float* __restrict__ bias, float* __restrict__ C)
{
    __shared__ float As[8][128];
    __shared__ float Bs[8][128];

    const int tid = threadIdx.x;
    const int n0 = blockIdx.x * 128;
    const int m0 = blockIdx.y * 128;

    // thread tile mapping: for MODE 0 we want consecutive tids -> consecutive m
    // (coalesced transposed stores); for MODE 1 consecutive tids -> consecutive n.
    const int tx = tid & 15;
    const int ty = tid >> 4;
    const int mB = (MODE == 0 ? tx : ty) * 4;
    const int nB = (MODE == 0 ? ty : tx) * 4;

    float acc[8][8];
#pragma unroll
    for (int i = 0; i < 8; i++)
#pragma unroll
        for (int j = 0; j < 8; j++) acc[i][j] = 0.0f;

    for (int kt = 0; kt < DMODEL; kt += 8) {
        __syncthreads();
        // --- load A tile [128 m x 8 k] ---
        if (MODE == 0) {
            const int mm = tid >> 1;
            const int kk = (tid & 1) * 4;
            const float4 av = *(const float4*)(A + (size_t)(m0 + mm) * DMODEL + kt + kk);
            As[kk + 0][mm] = av.x;
            As[kk + 1][mm] = av.y;
            As[kk + 2][mm] = av.z;
            As[kk + 3][mm] = av.w;
        } else {
            const int k  = tid >> 5;
            const int mo = (tid & 31) * 4;
            const int b  = m0 >> 12;
            const int l0 = m0 & (LSEQ - 1);
            const float4 av = *(const float4*)(A + ((size_t)b * DMODEL + kt + k) * LSEQ + l0 + mo);
            *(float4*)&As[k][mo] = av;
        }
        // --- load B tile [8 k x 128 n] ---
        {
            const int k  = tid >> 5;
            const int no = (tid & 31) * 4;
            const float4 bv = *(const float4*)(W + (size_t)(kt + k) * DMODEL + n0 + no);
            *(float4*)&Bs[k][no] = bv;
        }
        __syncthreads();

#pragma unroll
        for (int k = 0; k < 8; k++) {
            float a[8], b[8];
#pragma unroll
            for (int i = 0; i < 4; i++) {
                a[i]     = As[k][mB + i];
                a[i + 4] = As[k][64 + mB + i];
                b[i]     = Bs[k][nB + i];
                b[i + 4] = Bs[k][64 + nB + i];
            }
#pragma unroll
            for (int i = 0; i < 8; i++)
#pragma unroll
                for (int j = 0; j < 8; j++)
                    acc[i][j] += a[i] * b[j];
        }
    }

    // --- epilogue ---
#pragma unroll
    for (int j = 0; j < 8; j++) {
        const int n = n0 + nB + (j < 4 ? j : 60 + j);
        const float bv = bias[n];
#pragma unroll
        for (int i = 0; i < 8; i++) {
            const int m = m0 + mB + (i < 4 ? i : 60 + i);
            const float val = acc[i][j] + bv;
            if (MODE == 0) {
                const int b = m >> 12;
                const int l = m & (LSEQ - 1);
                C[((size_t)b * DMODEL + n) * LSEQ + l] = val;
            } else {
                C[(size_t)m * DMODEL + n] = val;
            }
        }
    }
}

// ---------------------------------------------------------------------------
// Fused correlation kernel: per row (b,h,d):
//   corr = irfft(rfft(q) * conj(rfft(k)))  via one complex FFT (z = q + i k)
//   top-16 -> softmax -> agg[t] = sum_i w_i * v[(t + d_i) mod L]
// 8192 blocks x 512 threads. Stockham radix-2 FFT, ping-pong in smem.
// ---------------------------------------------------------------------------
#define CORR_SMEM_BYTES (2 * LSEQ * 8 + LSEQ * 4 + 64 * 4)

__device__ __forceinline__ void fft4096(float2* buf0, float2* buf1, int tid)
{
    // 12 radix-2 Stockham stages; result ends back in buf0.
    float2* src = buf0;
    float2* dst = buf1;
    int l = LSEQ / 2, m = 1;
    for (int st = 0; st < 12; st++) {
        __syncthreads();
        for (int idx = tid; idx < LSEQ / 2; idx += 512) {
            const int j = idx >> st;        // idx / m
            const int k = idx & (m - 1);
            const float2 c0 = src[j * m + k];
            const float2 c1 = src[j * m + k + LSEQ / 2];
            const float ang = -3.14159265358979323846f * (float)j / (float)l;
            float sw, cw;
            __sincosf(ang, &sw, &cw);
            const float dx = c0.x - c1.x;
            const float dy = c0.y - c1.y;
            dst[2 * j * m + k]     = make_float2(c0.x + c1.x, c0.y + c1.y);
            dst[2 * j * m + k + m] = make_float2(cw * dx - sw * dy, cw * dy + sw * dx);
        }
        float2* t = src; src = dst; dst = t;
        l >>= 1; m <<= 1;
    }
    __syncthreads();
}

__global__ void __launch_bounds__(512, 1) corr_kernel(
    const float* __restrict__ qT, const float* __restrict__ kT,
    const float* __restrict__ vT, float* __restrict__ aT)
{
    extern __shared__ float smem[];
    float2* Az   = (float2*)smem;            // 4096 complex
    float2* Bz   = Az + LSEQ;                // 4096 complex
    float*  vbuf = (float*)(Bz + LSEQ);      // 4096 floats
    float*  rval = vbuf + LSEQ;              // 16 warp partial vals
    int*    ridx = (int*)(rval + 16);        // 16 warp partial idx
    float*  wts  = (float*)(ridx + 16);      // 16 topk weights
    int*    dly  = (int*)(wts + 16);         // 16 topk delays

    const int tid = threadIdx.x;
    const size_t row = blockIdx.x;
    const float* qp = qT + row * LSEQ;
    const float* kp = kT + row * LSEQ;
    const float* vp = vT + row * LSEQ;

    for (int i = tid; i < LSEQ; i += 512) {
        Az[i] = make_float2(qp[i], kp[i]);
        vbuf[i] = vp[i];
    }

    // forward FFT of z = q + i k   (result in Az)
    fft4096(Az, Bz, tid);

    // spectrum: Q = (Z[f] + conj(Z[-f]))/2, K = -i(Z[f] - conj(Z[-f]))/2
    // S = Q * conj(K); store conj(S) so a forward FFT gives N * corr
    for (int f = tid; f < LSEQ; f += 512) {
        const float2 zf = Az[f];
        const float2 zc = Az[(LSEQ - f) & (LSEQ - 1)];
        const float qx = 0.5f * (zf.x + zc.x);
        const float qy = 0.5f * (zf.y - zc.y);
        const float dx = 0.5f * (zf.x - zc.x);
        const float dy = 0.5f * (zf.y + zc.y);
        const float kx = dy;        // K = -i * d
        const float ky = -dx;
        const float sx = qx * kx + qy * ky;   // S = Q * conj(K)
        const float sy = qy * kx - qx * ky;
        Bz[f] = make_float2(sx, -sy);          // conj(S)
    }

    // forward FFT of conj(S) -> real part = N * corr  (result in Bz)
    fft4096(Bz, Az, tid);

    // ---- top-16 by 16 sequential argmax reductions over Bz[.].x ----
    const int lane = tid & 31;
    const int wid  = tid >> 5;
    for (int it = 0; it < TOPK; it++) {
        float best = -INFINITY;
        int   bi   = LSEQ;
        for (int i = tid; i < LSEQ; i += 512) {
            const float v = Bz[i].x;
            if (v > best || (v == best && i < bi)) { best = v; bi = i; }
        }
#pragma unroll
        for (int off = 16; off; off >>= 1) {
            const float ov = __shfl_down_sync(0xffffffffu, best, off);
            const int   oi = __shfl_down_sync(0xffffffffu, bi, off);
            if (ov > best || (ov == best && oi < bi)) { best = ov; bi = oi; }
        }
        if (lane == 0) { rval[wid] = best; ridx[wid] = bi; }
        __syncthreads();
        if (tid == 0) {
            float gb = rval[0]; int gi = ridx[0];
            for (int w = 1; w < 16; w++)
                if (rval[w] > gb || (rval[w] == gb && ridx[w] < gi)) { gb = rval[w]; gi = ridx[w]; }
            wts[it] = gb * (1.0f / (float)LSEQ);   // undo FFT scale -> true corr
            dly[it] = gi;
            Bz[gi].x = -INFINITY;                  // mask for next iteration
        }
        __syncthreads();
    }

    // softmax over the 16 raw correlation values
    if (tid == 0) {
        float mx = wts[0];
        for (int i = 1; i < TOPK; i++) mx = fmaxf(mx, wts[i]);
        float s = 0.0f;
        for (int i = 0; i < TOPK; i++) { const float e = expf(wts[i] - mx); wts[i] = e; s += e; }
        const float inv = 1.0f / s;
        for (int i = 0; i < TOPK; i++) wts[i] *= inv;
    }
    __syncthreads();

    float w[TOPK];
    int   d[TOPK];
#pragma unroll
    for (int i = 0; i < TOPK; i++) { w[i] = wts[i]; d[i] = dly[i]; }

    float* outp = aT + row * LSEQ;
    for (int t = tid; t < LSEQ; t += 512) {
        float acc = 0.0f;
#pragma unroll
        for (int i = 0; i < TOPK; i++)
            acc += w[i] * vbuf[(t + d[i]) & (LSEQ - 1)];
        outp[t] = acc;
    }
}

// ---------------------------------------------------------------------------
// Launch
// ---------------------------------------------------------------------------
extern "C" void kernel_launch(void* const* d_in, const int* in_sizes, int n_in,
                              void* d_out, int out_size)
{
    const float* q  = (const float*)d_in[0];
    const float* k  = (const float*)d_in[1];
    const float* v  = (const float*)d_in[2];
    const float* Wq = (const float*)d_in[3];
    const float* bq = (const float*)d_in[4];
    const float* Wk = (const float*)d_in[5];
    const float* bk = (const float*)d_in[6];
    const float* Wv = (const float*)d_in[7];
    const float* bv = (const float*)d_in[8];
    const float* Wo = (const float*)d_in[9];
    const float* bo = (const float*)d_in[10];
    float* out = (float*)d_out;

    float *qT, *kT, *vT, *aT;
    cudaGetSymbolAddress((void**)&qT, g_qT);
    cudaGetSymbolAddress((void**)&kT, g_kT);
    cudaGetSymbolAddress((void**)&vT, g_vT);
    cudaGetSymbolAddress((void**)&aT, g_aT);

    cudaFuncSetAttribute(corr_kernel,
                         cudaFuncAttributeMaxDynamicSharedMemorySize,
                         CORR_SMEM_BYTES);

    const dim3 gg(DMODEL / 128, (NB * LSEQ) / 128);   // (8, 256)

    sgemm_kernel<0><<<gg, 256>>>(q, Wq, bq, qT);
    sgemm_kernel<0><<<gg, 256>>>(k, Wk, bk, kT);
    sgemm_kernel<0><<<gg, 256>>>(v, Wv, bv, vT);

    corr_kernel<<<NROWS, 512, CORR_SMEM_BYTES>>>(qT, kT, vT, aT);

    sgemm_kernel<1><<<gg, 256>>>(aT, Wo, bo, out);
}

// round 4
// speedup vs baseline: 1.8592x; 1.8592x over previous
#include <cuda_runtime.h>
#include <cuda_fp16.h>
#include <math.h>
#include <stdint.h>

#define NB      8
#define LSEQ    4096
#define DMODEL  1024
#define TOPK    16
#define NROWS   (NB * DMODEL)          // 8192
#define MTOT    (NB * LSEQ)            // 32768

// ---------------------------------------------------------------------------
// Scratch (device globals; no runtime allocation allowed)
// ---------------------------------------------------------------------------
__device__ float  g_qT[(size_t)NROWS * LSEQ];   // [b*1024 + hd][l] fp32
__device__ float  g_kT[(size_t)NROWS * LSEQ];
__device__ float  g_vT[(size_t)NROWS * LSEQ];
__device__ __half g_x_hi[(size_t)MTOT * DMODEL];   // row-major [m,k]
__device__ __half g_x_lo[(size_t)MTOT * DMODEL];
__device__ __half g_a_hi[(size_t)MTOT * DMODEL];   // batched [(b*1024+hd)*4096+l]
__device__ __half g_a_lo[(size_t)MTOT * DMODEL];
__device__ __half g_wt_hi[4 * DMODEL * DMODEL];    // W^T, [n,k], 4 matrices
__device__ __half g_wt_lo[4 * DMODEL * DMODEL];

extern __shared__ char smem_raw[];

// ---------------------------------------------------------------------------
// PTX helpers (baseline sm_80+ instructions only: cp.async / ldmatrix / mma)
// ---------------------------------------------------------------------------
__device__ __forceinline__ uint32_t smem_u32(const void* p) {
    uint32_t a;
    asm("{ .reg .u64 t; cvta.to.shared.u64 t, %1; cvt.u32.u64 %0, t; }" : "=r"(a) : "l"(p));
    return a;
}
__device__ __forceinline__ void cpa16(uint32_t d, const void* g) {
    asm volatile("cp.async.cg.shared.global [%0], [%1], 16;" :: "r"(d), "l"(g));
}
#define CPA_COMMIT() asm volatile("cp.async.commit_group;" ::: "memory")
#define CPA_WAIT(n)  asm volatile("cp.async.wait_group %0;" :: "n"(n) : "memory")

#define LDSM4(r0, r1, r2, r3, a) \
    asm volatile("ldmatrix.sync.aligned.m8n8.x4.shared.b16 {%0,%1,%2,%3}, [%4];" \
        : "=r"(r0), "=r"(r1), "=r"(r2), "=r"(r3) : "r"(a))

#define MMA16816(d, a, b) \
    asm volatile("mma.sync.aligned.m16n8k16.row.col.f32.f16.f16.f32 " \
        "{%0,%1,%2,%3}, {%4,%5,%6,%7}, {%8,%9}, {%0,%1,%2,%3};" \
        : "+f"((d)[0]), "+f"((d)[1]), "+f"((d)[2]), "+f"((d)[3]) \
        : "r"((a)[0]), "r"((a)[1]), "r"((a)[2]), "r"((a)[3]), "r"((b)[0]), "r"((b)[1]))

// ---------------------------------------------------------------------------
// Split conversion kernels (lo residual stored UNSCALED)
// ---------------------------------------------------------------------------
__global__ void __launch_bounds__(256) split_kernel(
    const float* __restrict__ in, __half* __restrict__ hi, __half* __restrict__ lo, int n4)
{
    const int i = blockIdx.x * 256 + threadIdx.x;
    if (i >= n4) return;
    const float4 v = ((const float4*)in)[i];
    const __half h0 = __float2half_rn(v.x);
    const __half h1 = __float2half_rn(v.y);
    const __half h2 = __float2half_rn(v.z);
    const __half h3 = __float2half_rn(v.w);
    ((__half2*)hi)[i * 2 + 0] = __halves2half2(h0, h1);
    ((__half2*)hi)[i * 2 + 1] = __halves2half2(h2, h3);
    ((__half2*)lo)[i * 2 + 0] = __halves2half2(
        __float2half_rn(v.x - __half2float(h0)), __float2half_rn(v.y - __half2float(h1)));
    ((__half2*)lo)[i * 2 + 1] = __halves2half2(
        __float2half_rn(v.z - __half2float(h2)), __float2half_rn(v.w - __half2float(h3)));
}

// W [k,n] -> W^T [n,k] hi/lo
__global__ void __launch_bounds__(256) wsplit_kernel(
    const float* __restrict__ W, __half* __restrict__ Thi, __half* __restrict__ Tlo)
{
    __shared__ float t[32][33];
    const int bx = blockIdx.x * 32;   // n block
    const int by = blockIdx.y * 32;   // k block
    const int tx = threadIdx.x & 31;
    const int ty = threadIdx.x >> 5;  // 0..7
#pragma unroll
    for (int j = 0; j < 4; j++)
        t[ty + j * 8][tx] = W[(size_t)(by + ty + j * 8) * DMODEL + bx + tx];
    __syncthreads();
#pragma unroll
    for (int j = 0; j < 4; j++) {
        const float v = t[tx][ty + j * 8];
        const __half h = __float2half_rn(v);
        const size_t o = (size_t)(bx + ty + j * 8) * DMODEL + by + tx;
        Thi[o] = h;
        Tlo[o] = __float2half_rn(v - __half2float(h));
    }
}

// ---------------------------------------------------------------------------
// Split-fp16 HMMA GEMM: C = A @ W + bias   (M=32768, N=1024, K=1024)
// CTA tile 128x128, 8 warps (2 m x 4 n), warp tile 64x32, K-slab 64,
// cp.async double-buffered.  One fp32 accumulator:
//    acc += hi*hi + hi*lo + lo*hi    (lo unscaled)
// MODE 0: A row-major [m,k]; C fp32 batched-transposed [(b*1024+n)*4096+l]
// MODE 1: A[m,k] = src[(b*1024+k)*4096 + l]; C row-major [m,n]
// ---------------------------------------------------------------------------
#define SA_HI 0
#define SA_LO 16384
#define SB_HI 32768
#define SB_LO 49152
#define STAGE 65536
#define GEMM_SMEM 131072
#define EPS 132   // epilogue row stride (floats)

__device__ __forceinline__ int swz(int r, int cb) {   // r: row, cb: byte col in [0,128)
    return r * 128 + (cb ^ ((r & 7) << 4));
}

template<int MODE>
__global__ void __launch_bounds__(256, 1) hgemm_kernel(
    const __half* __restrict__ Ahi, const __half* __restrict__ Alo,
    const __half* __restrict__ Bhi, const __half* __restrict__ Blo,
    const float* __restrict__ bias, float* __restrict__ C)
{
    char* smem = smem_raw;
    const int tid  = threadIdx.x;
    const int wid  = tid >> 5;
    const int lane = tid & 31;
    const int n0 = blockIdx.x * 128;
    const int m0 = blockIdx.y * 128;
    const int warp_m = wid & 1;        // 0..1
    const int warp_n = wid >> 1;       // 0..3
    const int bb = m0 >> 12;
    const int l0 = m0 & (LSEQ - 1);
    const uint32_t sbase = smem_u32(smem);

    float acc[4][4][4];
#pragma unroll
    for (int mi = 0; mi < 4; mi++)
#pragma unroll
        for (int ni = 0; ni < 4; ni++)
#pragma unroll
            for (int j = 0; j < 4; j++) acc[mi][ni][j] = 0.0f;

    auto load_stage = [&](int st, int kt) {
        const uint32_t sb = sbase + st * STAGE;
        char* buf = smem + st * STAGE;
        // B tiles (always row-major [n,k]) via cp.async
#pragma unroll
        for (int i = 0; i < 4; i++) {
            const int idx = tid + i * 256;
            const int r = idx >> 3, ch = idx & 7;
            const int sw = swz(r, ch * 16);
            const size_t go = (size_t)(n0 + r) * DMODEL + kt + ch * 8;
            cpa16(sb + SB_HI + sw, Bhi + go);
            cpa16(sb + SB_LO + sw, Blo + go);
        }
        if (MODE == 0) {
#pragma unroll
            for (int i = 0; i < 4; i++) {
                const int idx = tid + i * 256;
                const int r = idx >> 3, ch = idx & 7;
                const int sw = swz(r, ch * 16);
                const size_t go = (size_t)(m0 + r) * DMODEL + kt + ch * 8;
                cpa16(sb + SA_HI + sw, Ahi + go);
                cpa16(sb + SA_LO + sw, Alo + go);
            }
            CPA_COMMIT();
        } else {
            CPA_COMMIT();
            // gather A from batched layout: A[m][k] = src[(b*1024+kt+k)*4096 + l0 + m]
#pragma unroll
            for (int i = 0; i < 4; i++) {
                const int idx = tid + i * 256;
                const int k  = idx & 63;
                const int m  = (idx >> 6) * 8;
                const size_t go = ((size_t)(bb * DMODEL + kt + k)) * LSEQ + l0 + m;
                const float4 vh = *(const float4*)(Ahi + go);
                const float4 vl = *(const float4*)(Alo + go);
                const __half* hh = (const __half*)&vh;
                const __half* hl = (const __half*)&vl;
#pragma unroll
                for (int j = 0; j < 8; j++) {
                    const int sw = swz(m + j, k * 2);
                    *(__half*)(buf + SA_HI + sw) = hh[j];
                    *(__half*)(buf + SA_LO + sw) = hl[j];
                }
            }
        }
    };

    load_stage(0, 0);
    for (int s = 0; s < 16; s++) {
        if (s < 15) load_stage((s + 1) & 1, (s + 1) * 64);
        if (s < 15) { CPA_WAIT(1); } else { CPA_WAIT(0); }
        __syncthreads();

        const uint32_t sb = sbase + (s & 1) * STAGE;
#pragma unroll
        for (int kk = 0; kk < 4; kk++) {
            uint32_t ahi[4][4], alo[4][4], bhi[4][2], blo[4][2];
            // A fragments: warp rows warp_m*64 + mi*16
            const int ar = warp_m * 64 + (lane & 15);
            const int acb = kk * 32 + (lane >> 4) * 16;
#pragma unroll
            for (int mi = 0; mi < 4; mi++) {
                const int r = ar + mi * 16;
                const uint32_t ad = sb + swz(r, acb);
                LDSM4(ahi[mi][0], ahi[mi][1], ahi[mi][2], ahi[mi][3], ad + SA_HI);
                LDSM4(alo[mi][0], alo[mi][1], alo[mi][2], alo[mi][3], ad + SA_LO);
            }
            // B fragments: rows warp_n*32 + ni2*16 + (lane>>4)*8 + (lane&7)
            const int br = warp_n * 32 + ((lane >> 4) << 3) + (lane & 7);
            const int bcb = kk * 32 + ((lane >> 3) & 1) * 16;
#pragma unroll
            for (int ni2 = 0; ni2 < 2; ni2++) {
                const int r = br + ni2 * 16;
                const uint32_t bd = sb + swz(r, bcb);
                LDSM4(bhi[ni2 * 2][0], bhi[ni2 * 2][1], bhi[ni2 * 2 + 1][0], bhi[ni2 * 2 + 1][1], bd + SB_HI);
                LDSM4(blo[ni2 * 2][0], blo[ni2 * 2][1], blo[ni2 * 2 + 1][0], blo[ni2 * 2 + 1][1], bd + SB_LO);
            }
#pragma unroll
            for (int mi = 0; mi < 4; mi++)
#pragma unroll
                for (int ni = 0; ni < 4; ni++) {
                    MMA16816(acc[mi][ni], ahi[mi], bhi[ni]);
                    MMA16816(acc[mi][ni], ahi[mi], blo[ni]);
                    MMA16816(acc[mi][ni], alo[mi], bhi[ni]);
                }
        }
        __syncthreads();
    }

    // ---- epilogue: stage through smem for coalesced output ----
    float* ep = (float*)smem;
#pragma unroll
    for (int mi = 0; mi < 4; mi++) {
        const int r0 = warp_m * 64 + mi * 16 + (lane >> 2);
#pragma unroll
        for (int ni = 0; ni < 4; ni++) {
            const int c = warp_n * 32 + ni * 8 + 2 * (lane & 3);
            const float b0 = bias[n0 + c];
            const float b1 = bias[n0 + c + 1];
            if (MODE == 0) {
                ep[(c    ) * EPS + r0    ] = acc[mi][ni][0] + b0;
                ep[(c + 1) * EPS + r0    ] = acc[mi][ni][1] + b1;
                ep[(c    ) * EPS + r0 + 8] = acc[mi][ni][2] + b0;
                ep[(c + 1) * EPS + r0 + 8] = acc[mi][ni][3] + b1;
            } else {
                ep[(r0    ) * EPS + c    ] = acc[mi][ni][0] + b0;
                ep[(r0    ) * EPS + c + 1] = acc[mi][ni][1] + b1;
                ep[(r0 + 8) * EPS + c    ] = acc[mi][ni][2] + b0;
                ep[(r0 + 8) * EPS + c + 1] = acc[mi][ni][3] + b1;
            }
        }
    }
    __syncthreads();
#pragma unroll
    for (int j = 0; j < 16; j++) {
        const int row = j * 8 + wid;      // MODE0: n index; MODE1: m index
        const float4 v = *(const float4*)(ep + row * EPS + lane * 4);
        if (MODE == 0)
            *(float4*)(C + ((size_t)(bb * DMODEL + n0 + row)) * LSEQ + l0 + lane * 4) = v;
        else
            *(float4*)(C + (size_t)(m0 + row) * DMODEL + n0 + lane * 4) = v;
    }
}

// ---------------------------------------------------------------------------
// Fused correlation kernel (unchanged math; outputs unscaled hi/lo halves)
// ---------------------------------------------------------------------------
#define CORR_SMEM_BYTES (2 * LSEQ * 8 + LSEQ * 4 + 64 * 4)

__device__ __forceinline__ void fft4096(float2* buf0, float2* buf1, int tid)
{
    float2* src = buf0;
    float2* dst = buf1;
    int l = LSEQ / 2, m = 1;
    for (int st = 0; st < 12; st++) {
        __syncthreads();
        for (int idx = tid; idx < LSEQ / 2; idx += 512) {
            const int j = idx >> st;
            const int k = idx & (m - 1);
            const float2 c0 = src[j * m + k];
            const float2 c1 = src[j * m + k + LSEQ / 2];
            const float ang = -3.14159265358979323846f * (float)j / (float)l;
            float sw, cw;
            __sincosf(ang, &sw, &cw);
            const float dx = c0.x - c1.x;
            const float dy = c0.y - c1.y;
            dst[2 * j * m + k]     = make_float2(c0.x + c1.x, c0.y + c1.y);
            dst[2 * j * m + k + m] = make_float2(cw * dx - sw * dy, cw * dy + sw * dx);
        }
        float2* t = src; src = dst; dst = t;
        l >>= 1; m <<= 1;
    }
    __syncthreads();
}

__global__ void __launch_bounds__(512, 1) corr_kernel(
    const float* __restrict__ qT, const float* __restrict__ kT,
    const float* __restrict__ vT, __half* __restrict__ aHi, __half* __restrict__ aLo)
{
    float* smem = (float*)smem_raw;
    float2* Az   = (float2*)smem;
    float2* Bz   = Az + LSEQ;
    float*  vbuf = (float*)(Bz + LSEQ);
    float*  rval = vbuf + LSEQ;
    int*    ridx = (int*)(rval + 16);
    float*  wts  = (float*)(ridx + 16);
    int*    dly  = (int*)(wts + 16);

    const int tid = threadIdx.x;
    const size_t row = blockIdx.x;
    const float* qp = qT + row * LSEQ;
    const float* kp = kT + row * LSEQ;
    const float* vp = vT + row * LSEQ;

    for (int i = tid; i < LSEQ; i += 512) {
        Az[i] = make_float2(qp[i], kp[i]);
        vbuf[i] = vp[i];
    }

    fft4096(Az, Bz, tid);

    for (int f = tid; f < LSEQ; f += 512) {
        const float2 zf = Az[f];
        const float2 zc = Az[(LSEQ - f) & (LSEQ - 1)];
        const float qx = 0.5f * (zf.x + zc.x);
        const float qy = 0.5f * (zf.y - zc.y);
        const float dx = 0.5f * (zf.x - zc.x);
        const float dy = 0.5f * (zf.y + zc.y);
        const float kx = dy;
        const float ky = -dx;
        const float sx = qx * kx + qy * ky;
        const float sy = qy * kx - qx * ky;
        Bz[f] = make_float2(sx, -sy);
    }

    fft4096(Bz, Az, tid);

    const int lane = tid & 31;
    const int wid  = tid >> 5;
    for (int it = 0; it < TOPK; it++) {
        float best = -INFINITY;
        int   bi   = LSEQ;
        for (int i = tid; i < LSEQ; i += 512) {
            const float v = Bz[i].x;
            if (v > best || (v == best && i < bi)) { best = v; bi = i; }
        }
#pragma unroll
        for (int off = 16; off; off >>= 1) {
            const float ov = __shfl_down_sync(0xffffffffu, best, off);
            const int   oi = __shfl_down_sync(0xffffffffu, bi, off);
            if (ov > best || (ov == best && oi < bi)) { best = ov; bi = oi; }
        }
        if (lane == 0) { rval[wid] = best; ridx[wid] = bi; }
        __syncthreads();
        if (tid == 0) {
            float gb = rval[0]; int gi = ridx[0];
            for (int w = 1; w < 16; w++)
                if (rval[w] > gb || (rval[w] == gb && ridx[w] < gi)) { gb = rval[w]; gi = ridx[w]; }
            wts[it] = gb * (1.0f / (float)LSEQ);
            dly[it] = gi;
            Bz[gi].x = -INFINITY;
        }
        __syncthreads();
    }

    if (tid == 0) {
        float mx = wts[0];
        for (int i = 1; i < TOPK; i++) mx = fmaxf(mx, wts[i]);
        float s = 0.0f;
        for (int i = 0; i < TOPK; i++) { const float e = expf(wts[i] - mx); wts[i] = e; s += e; }
        const float inv = 1.0f / s;
        for (int i = 0; i < TOPK; i++) wts[i] *= inv;
    }
    __syncthreads();

    float w[TOPK];
    int   d[TOPK];
#pragma unroll
    for (int i = 0; i < TOPK; i++) { w[i] = wts[i]; d[i] = dly[i]; }

    __half* oh = aHi + row * LSEQ;
    __half* ol = aLo + row * LSEQ;
    for (int t = tid; t < LSEQ; t += 512) {
        float acc = 0.0f;
#pragma unroll
        for (int i = 0; i < TOPK; i++)
            acc += w[i] * vbuf[(t + d[i]) & (LSEQ - 1)];
        const __half h = __float2half_rn(acc);
        oh[t] = h;
        ol[t] = __float2half_rn(acc - __half2float(h));
    }
}

// ---------------------------------------------------------------------------
// Launch
// ---------------------------------------------------------------------------
extern "C" void kernel_launch(void* const* d_in, const int* in_sizes, int n_in,
                              void* d_out, int out_size)
{
    const float* q  = (const float*)d_in[0];
    const float* k  = (const float*)d_in[1];
    const float* v  = (const float*)d_in[2];
    const float* Wq = (const float*)d_in[3];
    const float* bq = (const float*)d_in[4];
    const float* Wk = (const float*)d_in[5];
    const float* bk = (const float*)d_in[6];
    const float* Wv = (const float*)d_in[7];
    const float* bv = (const float*)d_in[8];
    const float* Wo = (const float*)d_in[9];
    const float* bo = (const float*)d_in[10];
    float* out = (float*)d_out;

    float  *qT, *kT, *vT;
    __half *xhi, *xlo, *ahi, *alo, *wthi, *wtlo;
    cudaGetSymbolAddress((void**)&qT,   g_qT);
    cudaGetSymbolAddress((void**)&kT,   g_kT);
    cudaGetSymbolAddress((void**)&vT,   g_vT);
    cudaGetSymbolAddress((void**)&xhi,  g_x_hi);
    cudaGetSymbolAddress((void**)&xlo,  g_x_lo);
    cudaGetSymbolAddress((void**)&ahi,  g_a_hi);
    cudaGetSymbolAddress((void**)&alo,  g_a_lo);
    cudaGetSymbolAddress((void**)&wthi, g_wt_hi);
    cudaGetSymbolAddress((void**)&wtlo, g_wt_lo);

    cudaFuncSetAttribute(hgemm_kernel<0>, cudaFuncAttributeMaxDynamicSharedMemorySize, GEMM_SMEM);
    cudaFuncSetAttribute(hgemm_kernel<1>, cudaFuncAttributeMaxDynamicSharedMemorySize, GEMM_SMEM);
    cudaFuncSetAttribute(corr_kernel,     cudaFuncAttributeMaxDynamicSharedMemorySize, CORR_SMEM_BYTES);

    const int WSZ = DMODEL * DMODEL;
    const dim3 wgrid(32, 32);
    wsplit_kernel<<<wgrid, 256>>>(Wq, wthi + 0 * WSZ, wtlo + 0 * WSZ);
    wsplit_kernel<<<wgrid, 256>>>(Wk, wthi + 1 * WSZ, wtlo + 1 * WSZ);
    wsplit_kernel<<<wgrid, 256>>>(Wv, wthi + 2 * WSZ, wtlo + 2 * WSZ);
    wsplit_kernel<<<wgrid, 256>>>(Wo, wthi + 3 * WSZ, wtlo + 3 * WSZ);

    const int n4 = MTOT * DMODEL / 4;
    const dim3 gg(DMODEL / 128, MTOT / 128);   // (8, 256)

    split_kernel<<<n4 / 256, 256>>>(q, xhi, xlo, n4);
    hgemm_kernel<0><<<gg, 256, GEMM_SMEM>>>(xhi, xlo, wthi + 0 * WSZ, wtlo + 0 * WSZ, bq, qT);
    split_kernel<<<n4 / 256, 256>>>(k, xhi, xlo, n4);
    hgemm_kernel<0><<<gg, 256, GEMM_SMEM>>>(xhi, xlo, wthi + 1 * WSZ, wtlo + 1 * WSZ, bk, kT);
    split_kernel<<<n4 / 256, 256>>>(v, xhi, xlo, n4);
    hgemm_kernel<0><<<gg, 256, GEMM_SMEM>>>(xhi, xlo, wthi + 2 * WSZ, wtlo + 2 * WSZ, bv, vT);

    corr_kernel<<<NROWS, 512, CORR_SMEM_BYTES>>>(qT, kT, vT, ahi, alo);

    hgemm_kernel<1><<<gg, 256, GEMM_SMEM>>>(ahi, alo, wthi + 3 * WSZ, wtlo + 3 * WSZ, bo, out);
}

// round 5
// speedup vs baseline: 2.1682x; 1.1662x over previous
#include <cuda_runtime.h>
#include <cuda_fp16.h>
#include <math.h>
#include <stdint.h>

#define NB      8
#define LSEQ    4096
#define DMODEL  1024
#define TOPK    16
#define NROWS   (NB * DMODEL)          // 8192
#define MTOT    (NB * LSEQ)            // 32768

// ---------------------------------------------------------------------------
// Scratch (device globals; no runtime allocation allowed)
// ---------------------------------------------------------------------------
__device__ float  g_qT[(size_t)NROWS * LSEQ];   // [b*1024 + hd][l] fp32
__device__ float  g_kT[(size_t)NROWS * LSEQ];
__device__ float  g_vT[(size_t)NROWS * LSEQ];
__device__ __half g_x_hi[3][(size_t)MTOT * DMODEL];   // row-major [m,k], q/k/v
__device__ __half g_x_lo[3][(size_t)MTOT * DMODEL];
__device__ __half g_a_hi[(size_t)MTOT * DMODEL];      // batched [(b*1024+hd)*4096+l]
__device__ __half g_a_lo[(size_t)MTOT * DMODEL];
__device__ __half g_wt_hi[4 * DMODEL * DMODEL];       // W^T, [n,k], 4 matrices
__device__ __half g_wt_lo[4 * DMODEL * DMODEL];

extern __shared__ char smem_raw[];

// ---------------------------------------------------------------------------
// PTX helpers (baseline sm_80+: cp.async / ldmatrix / mma)
// ---------------------------------------------------------------------------
__device__ __forceinline__ uint32_t smem_u32(const void* p) {
    uint32_t a;
    asm("{ .reg .u64 t; cvta.to.shared.u64 t, %1; cvt.u32.u64 %0, t; }" : "=r"(a) : "l"(p));
    return a;
}
__device__ __forceinline__ void cpa16(uint32_t d, const void* g) {
    asm volatile("cp.async.cg.shared.global [%0], [%1], 16;" :: "r"(d), "l"(g));
}
#define CPA_COMMIT() asm volatile("cp.async.commit_group;" ::: "memory")
#define CPA_WAIT(n)  asm volatile("cp.async.wait_group %0;" :: "n"(n) : "memory")

#define LDSM4(r0, r1, r2, r3, a) \
    asm volatile("ldmatrix.sync.aligned.m8n8.x4.shared.b16 {%0,%1,%2,%3}, [%4];" \
        : "=r"(r0), "=r"(r1), "=r"(r2), "=r"(r3) : "r"(a))

#define MMA16816(d, a, b) \
    asm volatile("mma.sync.aligned.m16n8k16.row.col.f32.f16.f16.f32 " \
        "{%0,%1,%2,%3}, {%4,%5,%6,%7}, {%8,%9}, {%0,%1,%2,%3};" \
        : "+f"((d)[0]), "+f"((d)[1]), "+f"((d)[2]), "+f"((d)[3]) \
        : "r"((a)[0]), "r"((a)[1]), "r"((a)[2]), "r"((a)[3]), "r"((b)[0]), "r"((b)[1]))

// ---------------------------------------------------------------------------
// Split conversion kernels (lo residual stored UNSCALED)
// ---------------------------------------------------------------------------
__global__ void __launch_bounds__(256) split_kernel(
    const float* __restrict__ in, __half* __restrict__ hi, __half* __restrict__ lo, int n4)
{
    const int i = blockIdx.x * 256 + threadIdx.x;
    if (i >= n4) return;
    const float4 v = ((const float4*)in)[i];
    const __half h0 = __float2half_rn(v.x);
    const __half h1 = __float2half_rn(v.y);
    const __half h2 = __float2half_rn(v.z);
    const __half h3 = __float2half_rn(v.w);
    ((__half2*)hi)[i * 2 + 0] = __halves2half2(h0, h1);
    ((__half2*)hi)[i * 2 + 1] = __halves2half2(h2, h3);
    ((__half2*)lo)[i * 2 + 0] = __halves2half2(
        __float2half_rn(v.x - __half2float(h0)), __float2half_rn(v.y - __half2float(h1)));
    ((__half2*)lo)[i * 2 + 1] = __halves2half2(
        __float2half_rn(v.z - __half2float(h2)), __float2half_rn(v.w - __half2float(h3)));
}

// W [k,n] -> W^T [n,k] hi/lo
__global__ void __launch_bounds__(256) wsplit_kernel(
    const float* __restrict__ W, __half* __restrict__ Thi, __half* __restrict__ Tlo)
{
    __shared__ float t[32][33];
    const int bx = blockIdx.x * 32;   // n block
    const int by = blockIdx.y * 32;   // k block
    const int tx = threadIdx.x & 31;
    const int ty = threadIdx.x >> 5;  // 0..7
#pragma unroll
    for (int j = 0; j < 4; j++)
        t[ty + j * 8][tx] = W[(size_t)(by + ty + j * 8) * DMODEL + bx + tx];
    __syncthreads();
#pragma unroll
    for (int j = 0; j < 4; j++) {
        const float v = t[tx][ty + j * 8];
        const __half h = __float2half_rn(v);
        const size_t o = (size_t)(bx + ty + j * 8) * DMODEL + by + tx;
        Thi[o] = h;
        Tlo[o] = __float2half_rn(v - __half2float(h));
    }
}

// ---------------------------------------------------------------------------
// Split-fp16 HMMA GEMM (pass-major MMA ordering for ILP)
// CTA tile 128x128, 8 warps (2m x 4n), warp tile 64x32, K-slab 64, 2-stage cp.async
//    acc += hi*hi ; acc += hi*lo ; acc += lo*hi    (each pass sweeps 16 indep accs)
// MODE 0: A row-major [m,k]; C fp32 batched-transposed [(b*1024+n)*4096+l]
// MODE 1: A[m,k] = src[(b*1024+k)*4096 + l]; C row-major [m,n]
// ---------------------------------------------------------------------------
#define SA_HI 0
#define SA_LO 16384
#define SB_HI 32768
#define SB_LO 49152
#define STAGE 65536
#define GEMM_SMEM 131072
#define EPS 132

__device__ __forceinline__ int swz(int r, int cb) {
    return r * 128 + (cb ^ ((r & 7) << 4));
}

template<int MODE>
__global__ void __launch_bounds__(256, 1) hgemm_kernel(
    const __half* __restrict__ Ahi, const __half* __restrict__ Alo,
    const __half* __restrict__ Bhi, const __half* __restrict__ Blo,
    const float* __restrict__ bias, float* __restrict__ C)
{
    char* smem = smem_raw;
    const int tid  = threadIdx.x;
    const int wid  = tid >> 5;
    const int lane = tid & 31;
    const int n0 = blockIdx.x * 128;
    const int m0 = blockIdx.y * 128;
    const int warp_m = wid & 1;
    const int warp_n = wid >> 1;
    const int bb = m0 >> 12;
    const int l0 = m0 & (LSEQ - 1);
    const uint32_t sbase = smem_u32(smem);

    float acc[4][4][4];
#pragma unroll
    for (int mi = 0; mi < 4; mi++)
#pragma unroll
        for (int ni = 0; ni < 4; ni++)
#pragma unroll
            for (int j = 0; j < 4; j++) acc[mi][ni][j] = 0.0f;

    auto load_stage = [&](int st, int kt) {
        const uint32_t sb = sbase + st * STAGE;
        char* buf = smem + st * STAGE;
#pragma unroll
        for (int i = 0; i < 4; i++) {
            const int idx = tid + i * 256;
            const int r = idx >> 3, ch = idx & 7;
            const int sw = swz(r, ch * 16);
            const size_t go = (size_t)(n0 + r) * DMODEL + kt + ch * 8;
            cpa16(sb + SB_HI + sw, Bhi + go);
            cpa16(sb + SB_LO + sw, Blo + go);
        }
        if (MODE == 0) {
#pragma unroll
            for (int i = 0; i < 4; i++) {
                const int idx = tid + i * 256;
                const int r = idx >> 3, ch = idx & 7;
                const int sw = swz(r, ch * 16);
                const size_t go = (size_t)(m0 + r) * DMODEL + kt + ch * 8;
                cpa16(sb + SA_HI + sw, Ahi + go);
                cpa16(sb + SA_LO + sw, Alo + go);
            }
            CPA_COMMIT();
        } else {
            CPA_COMMIT();
#pragma unroll
            for (int i = 0; i < 4; i++) {
                const int idx = tid + i * 256;
                const int k  = idx & 63;
                const int m  = (idx >> 6) * 8;
                const size_t go = ((size_t)(bb * DMODEL + kt + k)) * LSEQ + l0 + m;
                const float4 vh = *(const float4*)(Ahi + go);
                const float4 vl = *(const float4*)(Alo + go);
                const __half* hh = (const __half*)&vh;
                const __half* hl = (const __half*)&vl;
#pragma unroll
                for (int j = 0; j < 8; j++) {
                    const int sw = swz(m + j, k * 2);
                    *(__half*)(buf + SA_HI + sw) = hh[j];
                    *(__half*)(buf + SA_LO + sw) = hl[j];
                }
            }
        }
    };

    load_stage(0, 0);
    for (int s = 0; s < 16; s++) {
        if (s < 15) load_stage((s + 1) & 1, (s + 1) * 64);
        if (s < 15) { CPA_WAIT(1); } else { CPA_WAIT(0); }
        __syncthreads();

        const uint32_t sb = sbase + (s & 1) * STAGE;
#pragma unroll
        for (int kk = 0; kk < 4; kk++) {
            uint32_t ahi[4][4], alo[4][4], bhi[4][2], blo[4][2];
            const int ar = warp_m * 64 + (lane & 15);
            const int acb = kk * 32 + (lane >> 4) * 16;
#pragma unroll
            for (int mi = 0; mi < 4; mi++) {
                const int r = ar + mi * 16;
                const uint32_t ad = sb + swz(r, acb);
                LDSM4(ahi[mi][0], ahi[mi][1], ahi[mi][2], ahi[mi][3], ad + SA_HI);
                LDSM4(alo[mi][0], alo[mi][1], alo[mi][2], alo[mi][3], ad + SA_LO);
            }
            const int br = warp_n * 32 + ((lane >> 4) << 3) + (lane & 7);
            const int bcb = kk * 32 + ((lane >> 3) & 1) * 16;
#pragma unroll
            for (int ni2 = 0; ni2 < 2; ni2++) {
                const int r = br + ni2 * 16;
                const uint32_t bd = sb + swz(r, bcb);
                LDSM4(bhi[ni2 * 2][0], bhi[ni2 * 2][1], bhi[ni2 * 2 + 1][0], bhi[ni2 * 2 + 1][1], bd + SB_HI);
                LDSM4(blo[ni2 * 2][0], blo[ni2 * 2][1], blo[ni2 * 2 + 1][0], blo[ni2 * 2 + 1][1], bd + SB_LO);
            }
            // pass-major: 16 independent accumulators between reuses
#pragma unroll
            for (int mi = 0; mi < 4; mi++)
#pragma unroll
                for (int ni = 0; ni < 4; ni++)
                    MMA16816(acc[mi][ni], ahi[mi], bhi[ni]);
#pragma unroll
            for (int mi = 0; mi < 4; mi++)
#pragma unroll
                for (int ni = 0; ni < 4; ni++)
                    MMA16816(acc[mi][ni], ahi[mi], blo[ni]);
#pragma unroll
            for (int mi = 0; mi < 4; mi++)
#pragma unroll
                for (int ni = 0; ni < 4; ni++)
                    MMA16816(acc[mi][ni], alo[mi], bhi[ni]);
        }
        __syncthreads();
    }

    // ---- epilogue via smem for coalesced stores ----
    float* ep = (float*)smem;
#pragma unroll
    for (int mi = 0; mi < 4; mi++) {
        const int r0 = warp_m * 64 + mi * 16 + (lane >> 2);
#pragma unroll
        for (int ni = 0; ni < 4; ni++) {
            const int c = warp_n * 32 + ni * 8 + 2 * (lane & 3);
            const float b0 = bias[n0 + c];
            const float b1 = bias[n0 + c + 1];
            if (MODE == 0) {
                ep[(c    ) * EPS + r0    ] = acc[mi][ni][0] + b0;
                ep[(c + 1) * EPS + r0    ] = acc[mi][ni][1] + b1;
                ep[(c    ) * EPS + r0 + 8] = acc[mi][ni][2] + b0;
                ep[(c + 1) * EPS + r0 + 8] = acc[mi][ni][3] + b1;
            } else {
                ep[(r0    ) * EPS + c    ] = acc[mi][ni][0] + b0;
                ep[(r0    ) * EPS + c + 1] = acc[mi][ni][1] + b1;
                ep[(r0 + 8) * EPS + c    ] = acc[mi][ni][2] + b0;
                ep[(r0 + 8) * EPS + c + 1] = acc[mi][ni][3] + b1;
            }
        }
    }
    __syncthreads();
#pragma unroll
    for (int j = 0; j < 16; j++) {
        const int row = j * 8 + wid;
        const float4 v = *(const float4*)(ep + row * EPS + lane * 4);
        if (MODE == 0)
            *(float4*)(C + ((size_t)(bb * DMODEL + n0 + row)) * LSEQ + l0 + lane * 4) = v;
        else
            *(float4*)(C + (size_t)(m0 + row) * DMODEL + n0 + lane * 4) = v;
    }
}

// ---------------------------------------------------------------------------
// Fused correlation kernel: radix-4 Stockham FFT + register-resident top-16
// ---------------------------------------------------------------------------
#define CORR_SMEM_BYTES (2 * LSEQ * 8 + LSEQ * 4 + 64 * 4)

__device__ __forceinline__ void fft4096(float2* buf0, float2* buf1, int tid)
{
    // 6 radix-4 Stockham stages (== 12 verified radix-2 stages); result in buf0.
    float2* src = buf0;
    float2* dst = buf1;
    int m = 1;
    for (int st = 0; st < 6; st++) {
        __syncthreads();
#pragma unroll
        for (int h = 0; h < 2; h++) {
            const int idx = tid + h * 512;           // 0..1023
            const int k  = idx & (m - 1);
            const int Jm = idx - k;                  // J*m
            const float2 x0 = src[idx];
            const float2 x1 = src[idx + 1024];
            const float2 x2 = src[idx + 2048];
            const float2 x3 = src[idx + 3072];
            const float e0x = x0.x + x2.x, e0y = x0.y + x2.y;
            const float e1x = x0.x - x2.x, e1y = x0.y - x2.y;
            const float o0x = x1.x + x3.x, o0y = x1.y + x3.y;
            const float o1x = x1.x - x3.x, o1y = x1.y - x3.y;
            const float t3x = o1y, t3y = -o1x;       // -i*(x1-x3)
            const float ang = -1.5339807878856412e-3f * (float)Jm;  // -2pi/4096 * Jm
            float s1, c1;
            __sincosf(ang, &s1, &c1);
            const float c2 = c1 * c1 - s1 * s1, s2 = 2.0f * c1 * s1;
            const float c3 = c1 * c2 - s1 * s2, s3 = c1 * s2 + s1 * c2;
            const float u1x = e1x + t3x, u1y = e1y + t3y;
            const float u2x = e0x - o0x, u2y = e0y - o0y;
            const float u3x = e1x - t3x, u3y = e1y - t3y;
            const int base = idx + 3 * Jm;           // 4*J*m + k
            dst[base]         = make_float2(e0x + o0x, e0y + o0y);
            dst[base + m]     = make_float2(c1 * u1x - s1 * u1y, c1 * u1y + s1 * u1x);
            dst[base + 2 * m] = make_float2(c2 * u2x - s2 * u2y, c2 * u2y + s2 * u2x);
            dst[base + 3 * m] = make_float2(c3 * u3x - s3 * u3y, c3 * u3y + s3 * u3x);
        }
        float2* t = src; src = dst; dst = t;
        m <<= 2;
    }
    __syncthreads();
}

__global__ void __launch_bounds__(512, 1) corr_kernel(
    const float* __restrict__ qT, const float* __restrict__ kT,
    const float* __restrict__ vT, __half* __restrict__ aHi, __half* __restrict__ aLo)
{
    float* smem = (float*)smem_raw;
    float2* Az   = (float2*)smem;
    float2* Bz   = Az + LSEQ;
    float*  vbuf = (float*)(Bz + LSEQ);
    float*  rval = vbuf + LSEQ;
    int*    ridx = (int*)(rval + 16);
    float*  wts  = (float*)(ridx + 16);
    int*    dly  = (int*)(wts + 16);

    const int tid = threadIdx.x;
    const size_t row = blockIdx.x;
    const float* qp = qT + row * LSEQ;
    const float* kp = kT + row * LSEQ;
    const float* vp = vT + row * LSEQ;

#pragma unroll
    for (int i4 = tid; i4 < LSEQ / 4; i4 += 512) {
        const float4 q4 = ((const float4*)qp)[i4];
        const float4 k4 = ((const float4*)kp)[i4];
        const float4 v4 = ((const float4*)vp)[i4];
        Az[i4 * 4 + 0] = make_float2(q4.x, k4.x);
        Az[i4 * 4 + 1] = make_float2(q4.y, k4.y);
        Az[i4 * 4 + 2] = make_float2(q4.z, k4.z);
        Az[i4 * 4 + 3] = make_float2(q4.w, k4.w);
        *(float4*)(vbuf + i4 * 4) = v4;
    }

    fft4096(Az, Bz, tid);

    for (int f = tid; f < LSEQ; f += 512) {
        const float2 zf = Az[f];
        const float2 zc = Az[(LSEQ - f) & (LSEQ - 1)];
        const float qx = 0.5f * (zf.x + zc.x);
        const float qy = 0.5f * (zf.y - zc.y);
        const float dx = 0.5f * (zf.x - zc.x);
        const float dy = 0.5f * (zf.y + zc.y);
        const float kx = dy;
        const float ky = -dx;
        const float sx = qx * kx + qy * ky;
        const float sy = qy * kx - qx * ky;
        Bz[f] = make_float2(sx, -sy);
    }

    fft4096(Bz, Az, tid);

    // ---- register-resident top-16 ----
    const int lane = tid & 31;
    const int wrp  = tid >> 5;
    float cv[8];
#pragma unroll
    for (int c = 0; c < 8; c++) cv[c] = Bz[tid + 512 * c].x;

    for (int it = 0; it < TOPK; it++) {
        float best = cv[0];
        int   bc   = 0;
#pragma unroll
        for (int c = 1; c < 8; c++)
            if (cv[c] > best) { best = cv[c]; bc = c; }
        int bi = tid + 512 * bc;
#pragma unroll
        for (int off = 16; off; off >>= 1) {
            const float ov = __shfl_down_sync(0xffffffffu, best, off);
            const int   oi = __shfl_down_sync(0xffffffffu, bi, off);
            if (ov > best || (ov == best && oi < bi)) { best = ov; bi = oi; }
        }
        if (lane == 0) { rval[wrp] = best; ridx[wrp] = bi; }
        __syncthreads();
        if (tid < 32) {
            float v = (lane < 16) ? rval[lane] : -INFINITY;
            int   i = (lane < 16) ? ridx[lane] : LSEQ;
#pragma unroll
            for (int off = 8; off; off >>= 1) {
                const float ov = __shfl_down_sync(0xffffffffu, v, off);
                const int   oi = __shfl_down_sync(0xffffffffu, i, off);
                if (ov > v || (ov == v && oi < i)) { v = ov; i = oi; }
            }
            if (lane == 0) { wts[it] = v * (1.0f / (float)LSEQ); dly[it] = i; }
        }
        __syncthreads();
        const int gi = dly[it];
        if (tid == (gi & 511)) cv[gi >> 9] = -INFINITY;
    }

    if (tid == 0) {
        float mx = wts[0];
        for (int i = 1; i < TOPK; i++) mx = fmaxf(mx, wts[i]);
        float s = 0.0f;
        for (int i = 0; i < TOPK; i++) { const float e = expf(wts[i] - mx); wts[i] = e; s += e; }
        const float inv = 1.0f / s;
        for (int i = 0; i < TOPK; i++) wts[i] *= inv;
    }
    __syncthreads();

    float w[TOPK];
    int   d[TOPK];
#pragma unroll
    for (int i = 0; i < TOPK; i++) { w[i] = wts[i]; d[i] = dly[i]; }

    __half* oh = aHi + row * LSEQ;
    __half* ol = aLo + row * LSEQ;
    for (int t = tid; t < LSEQ; t += 512) {
        float acc = 0.0f;
#pragma unroll
        for (int i = 0; i < TOPK; i++)
            acc += w[i] * vbuf[(t + d[i]) & (LSEQ - 1)];
        const __half h = __float2half_rn(acc);
        oh[t] = h;
        ol[t] = __float2half_rn(acc - __half2float(h));
    }
}

// ---------------------------------------------------------------------------
// Launch
// ---------------------------------------------------------------------------
extern "C" void kernel_launch(void* const* d_in, const int* in_sizes, int n_in,
                              void* d_out, int out_size)
{
    const float* q  = (const float*)d_in[0];
    const float* k  = (const float*)d_in[1];
    const float* v  = (const float*)d_in[2];
    const float* Wq = (const float*)d_in[3];
    const float* bq = (const float*)d_in[4];
    const float* Wk = (const float*)d_in[5];
    const float* bk = (const float*)d_in[6];
    const float* Wv = (const float*)d_in[7];
    const float* bv = (const float*)d_in[8];
    const float* Wo = (const float*)d_in[9];
    const float* bo = (const float*)d_in[10];
    float* out = (float*)d_out;

    float  *qT, *kT, *vT;
    __half *xhi, *xlo, *ahi, *alo, *wthi, *wtlo;
    cudaGetSymbolAddress((void**)&qT,   g_qT);
    cudaGetSymbolAddress((void**)&kT,   g_kT);
    cudaGetSymbolAddress((void**)&vT,   g_vT);
    cudaGetSymbolAddress((void**)&xhi,  g_x_hi);
    cudaGetSymbolAddress((void**)&xlo,  g_x_lo);
    cudaGetSymbolAddress((void**)&ahi,  g_a_hi);
    cudaGetSymbolAddress((void**)&alo,  g_a_lo);
    cudaGetSymbolAddress((void**)&wthi, g_wt_hi);
    cudaGetSymbolAddress((void**)&wtlo, g_wt_lo);

    cudaFuncSetAttribute(hgemm_kernel<0>, cudaFuncAttributeMaxDynamicSharedMemorySize, GEMM_SMEM);
    cudaFuncSetAttribute(hgemm_kernel<1>, cudaFuncAttributeMaxDynamicSharedMemorySize, GEMM_SMEM);
    cudaFuncSetAttribute(corr_kernel,     cudaFuncAttributeMaxDynamicSharedMemorySize, CORR_SMEM_BYTES);

    const int WSZ = DMODEL * DMODEL;
    const size_t XSZ = (size_t)MTOT * DMODEL;
    const dim3 wgrid(32, 32);
    wsplit_kernel<<<wgrid, 256>>>(Wq, wthi + 0 * WSZ, wtlo + 0 * WSZ);
    wsplit_kernel<<<wgrid, 256>>>(Wk, wthi + 1 * WSZ, wtlo + 1 * WSZ);
    wsplit_kernel<<<wgrid, 256>>>(Wv, wthi + 2 * WSZ, wtlo + 2 * WSZ);
    wsplit_kernel<<<wgrid, 256>>>(Wo, wthi + 3 * WSZ, wtlo + 3 * WSZ);

    const int n4 = MTOT * DMODEL / 4;
    const dim3 gg(DMODEL / 128, MTOT / 128);   // (8, 256)

    split_kernel<<<n4 / 256, 256>>>(q, xhi + 0 * XSZ, xlo + 0 * XSZ, n4);
    split_kernel<<<n4 / 256, 256>>>(k, xhi + 1 * XSZ, xlo + 1 * XSZ, n4);
    split_kernel<<<n4 / 256, 256>>>(v, xhi + 2 * XSZ, xlo + 2 * XSZ, n4);

    hgemm_kernel<0><<<gg, 256, GEMM_SMEM>>>(xhi + 0 * XSZ, xlo + 0 * XSZ, wthi + 0 * WSZ, wtlo + 0 * WSZ, bq, qT);
    hgemm_kernel<0><<<gg, 256, GEMM_SMEM>>>(xhi + 1 * XSZ, xlo + 1 * XSZ, wthi + 1 * WSZ, wtlo + 1 * WSZ, bk, kT);
    hgemm_kernel<0><<<gg, 256, GEMM_SMEM>>>(xhi + 2 * XSZ, xlo + 2 * XSZ, wthi + 2 * WSZ, wtlo + 2 * WSZ, bv, vT);

    corr_kernel<<<NROWS, 512, CORR_SMEM_BYTES>>>(qT, kT, vT, ahi, alo);

    hgemm_kernel<1><<<gg, 256, GEMM_SMEM>>>(ahi, alo, wthi + 3 * WSZ, wtlo + 3 * WSZ, bo, out);
}

// round 7
// speedup vs baseline: 2.6508x; 1.2226x over previous
#include <cuda_runtime.h>
#include <cuda_fp16.h>
#include <math.h>
#include <stdint.h>

#define NB      8
#define LSEQ    4096
#define DMODEL  1024
#define TOPK    16
#define NROWS   (NB * DMODEL)          // 8192
#define MTOT    (NB * LSEQ)            // 32768

// ---------------------------------------------------------------------------
// Scratch (device globals; no runtime allocation allowed)
// ---------------------------------------------------------------------------
__device__ float  g_qT[(size_t)NROWS * LSEQ];   // [b*1024 + hd][l] fp32
__device__ float  g_kT[(size_t)NROWS * LSEQ];
__device__ float  g_vT[(size_t)NROWS * LSEQ];
__device__ __half g_a_hi[(size_t)MTOT * DMODEL];   // agg, batched [(b*1024+hd)*4096+l]
__device__ __half g_wt_hi[4 * DMODEL * DMODEL];    // W^T, [n,k], 4 matrices
__device__ __half g_wt_lo[4 * DMODEL * DMODEL];

extern __shared__ char smem_raw[];

// ---------------------------------------------------------------------------
// PTX helpers (baseline sm_80+: cp.async / ldmatrix / mma)
// ---------------------------------------------------------------------------
__device__ __forceinline__ uint32_t smem_u32(const void* p) {
    uint32_t a;
    asm("{ .reg .u64 t; cvta.to.shared.u64 t, %1; cvt.u32.u64 %0, t; }" : "=r"(a) : "l"(p));
    return a;
}
__device__ __forceinline__ void cpa16(uint32_t d, const void* g) {
    asm volatile("cp.async.cg.shared.global [%0], [%1], 16;" :: "r"(d), "l"(g));
}
#define CPA_COMMIT() asm volatile("cp.async.commit_group;" ::: "memory")
#define CPA_WAIT(n)  asm volatile("cp.async.wait_group %0;" :: "n"(n) : "memory")

#define LDSM4(r0, r1, r2, r3, a) \
    asm volatile("ldmatrix.sync.aligned.m8n8.x4.shared.b16 {%0,%1,%2,%3}, [%4];" \
        : "=r"(r0), "=r"(r1), "=r"(r2), "=r"(r3) : "r"(a))

#define MMA16816(d, a, b) \
    asm volatile("mma.sync.aligned.m16n8k16.row.col.f32.f16.f16.f32 " \
        "{%0,%1,%2,%3}, {%4,%5,%6,%7}, {%8,%9}, {%0,%1,%2,%3};" \
        : "+f"((d)[0]), "+f"((d)[1]), "+f"((d)[2]), "+f"((d)[3]) \
        : "r"((a)[0]), "r"((a)[1]), "r"((a)[2]), "r"((a)[3]), "r"((b)[0]), "r"((b)[1]))

// pack two halves into u32 (defined BEFORE first use)
__device__ __forceinline__ uint32_t halves2u32(__half a, __half b) {
    __half2 h = __halves2half2(a, b);
    return *(uint32_t*)&h;
}

// ---------------------------------------------------------------------------
// W [k,n] -> W^T [n,k] hi/lo split
// ---------------------------------------------------------------------------
__global__ void __launch_bounds__(256) wsplit_kernel(
    const float* __restrict__ W, __half* __restrict__ Thi, __half* __restrict__ Tlo)
{
    __shared__ float t[32][33];
    const int bx = blockIdx.x * 32;   // n block
    const int by = blockIdx.y * 32;   // k block
    const int tx = threadIdx.x & 31;
    const int ty = threadIdx.x >> 5;  // 0..7
#pragma unroll
    for (int j = 0; j < 4; j++)
        t[ty + j * 8][tx] = W[(size_t)(by + ty + j * 8) * DMODEL + bx + tx];
    __syncthreads();
#pragma unroll
    for (int j = 0; j < 4; j++) {
        const float v = t[tx][ty + j * 8];
        const __half h = __float2half_rn(v);
        const size_t o = (size_t)(bx + ty + j * 8) * DMODEL + by + tx;
        Thi[o] = h;
        Tlo[o] = __float2half_rn(v - __half2float(h));
    }
}

// ---------------------------------------------------------------------------
// Split-fp16 HMMA GEMM with fused on-the-fly A split.
// CTA 128x128, 8 warps (2m x 4n), K-slab 64, 2-stage.
// PASSES=3: acc = Ah*Bh + Ah*Bl + Al*Bh   (q,k projections)
// PASSES=2: acc = Ah*Bh + Ah*Bl           (v projection / output)
// MODE 0: A fp32 row-major [m,k], converted in-kernel;
//         C fp32 batched-transposed [(b*1024+n)*4096+l]
// MODE 1: A fp16 (hi only) batched: A[m,k] = src[(b*1024+k)*4096+l];
//         C fp32 row-major [m,n]
// ---------------------------------------------------------------------------
#define SA_HI 0
#define SA_LO 16384
#define SB_HI 32768
#define SB_LO 49152
#define STAGE 65536
#define GEMM_SMEM 131072
#define EPS 132

__device__ __forceinline__ int swz(int r, int cb) {
    return r * 128 + (cb ^ ((r & 7) << 4));
}

template<int MODE, int PASSES>
__global__ void __launch_bounds__(256, 1) hgemm_kernel(
    const void* __restrict__ Ain,
    const __half* __restrict__ Bhi, const __half* __restrict__ Blo,
    const float* __restrict__ bias, float* __restrict__ C)
{
    char* smem = smem_raw;
    const int tid  = threadIdx.x;
    const int wid  = tid >> 5;
    const int lane = tid & 31;
    const int n0 = blockIdx.x * 128;
    const int m0 = blockIdx.y * 128;
    const int warp_m = wid & 1;
    const int warp_n = wid >> 1;
    const int bb = m0 >> 12;
    const int l0 = m0 & (LSEQ - 1);
    const uint32_t sbase = smem_u32(smem);

    const float*  Af = (const float*)Ain;    // MODE 0
    const __half* Ah = (const __half*)Ain;   // MODE 1

    float acc[4][4][4];
#pragma unroll
    for (int mi = 0; mi < 4; mi++)
#pragma unroll
        for (int ni = 0; ni < 4; ni++)
#pragma unroll
            for (int j = 0; j < 4; j++) acc[mi][ni][j] = 0.0f;

    float4 ar[8];        // MODE 0 prefetch (fp32)
    float4 ar1[4];       // MODE 1 prefetch (halves)

    auto loadB = [&](int st, int kt) {
        const uint32_t sb = sbase + st * STAGE;
#pragma unroll
        for (int i = 0; i < 4; i++) {
            const int idx = tid + i * 256;
            const int r = idx >> 3, ch = idx & 7;
            const int sw = swz(r, ch * 16);
            const size_t go = (size_t)(n0 + r) * DMODEL + kt + ch * 8;
            cpa16(sb + SB_HI + sw, Bhi + go);
            cpa16(sb + SB_LO + sw, Blo + go);
        }
        CPA_COMMIT();
    };

    auto ldgA = [&](int kt) {
        if (MODE == 0) {
#pragma unroll
            for (int j = 0; j < 8; j++) {
                const int c = tid + j * 256;           // 2048 float4 chunks
                const int r = c >> 4, c4 = c & 15;
                ar[j] = *(const float4*)(Af + (size_t)(m0 + r) * DMODEL + kt + c4 * 4);
            }
        } else {
#pragma unroll
            for (int j = 0; j < 4; j++) {
                const int idx = tid + j * 256;
                const int k  = idx & 63;
                const int m  = (idx >> 6) * 8;
                ar1[j] = *(const float4*)(Ah + ((size_t)(bb * DMODEL + kt + k)) * LSEQ + l0 + m);
            }
        }
    };

    auto stsA = [&](int st) {
        char* buf = smem + st * STAGE;
        if (MODE == 0) {
#pragma unroll
            for (int j = 0; j < 8; j++) {
                const int c = tid + j * 256;
                const int r = c >> 4, c4 = c & 15;
                const float4 v = ar[j];
                const __half h0 = __float2half_rn(v.x);
                const __half h1 = __float2half_rn(v.y);
                const __half h2 = __float2half_rn(v.z);
                const __half h3 = __float2half_rn(v.w);
                const int o8 = r * 128 + ((c4 * 8) ^ ((r & 7) << 4));
                uint2 hh;
                hh.x = halves2u32(h0, h1);
                hh.y = halves2u32(h2, h3);
                *(uint2*)(buf + SA_HI + o8) = hh;
                if (PASSES == 3) {
                    uint2 ll;
                    ll.x = halves2u32(__float2half_rn(v.x - __half2float(h0)),
                                      __float2half_rn(v.y - __half2float(h1)));
                    ll.y = halves2u32(__float2half_rn(v.z - __half2float(h2)),
                                      __float2half_rn(v.w - __half2float(h3)));
                    *(uint2*)(buf + SA_LO + o8) = ll;
                }
            }
        } else {
#pragma unroll
            for (int j = 0; j < 4; j++) {
                const int idx = tid + j * 256;
                const int k  = idx & 63;
                const int m  = (idx >> 6) * 8;
                const __half* hh = (const __half*)&ar1[j];
#pragma unroll
                for (int q = 0; q < 8; q++)
                    *(__half*)(buf + SA_HI + swz(m + q, k * 2)) = hh[q];
            }
        }
    };

    // prologue
    loadB(0, 0);
    ldgA(0);
    stsA(0);

    for (int s = 0; s < 16; s++) {
        if (s < 15) { loadB((s + 1) & 1, (s + 1) * 64); ldgA((s + 1) * 64); }
        if (s < 15) { CPA_WAIT(1); } else { CPA_WAIT(0); }
        __syncthreads();

        const uint32_t sb = sbase + (s & 1) * STAGE;
#pragma unroll
        for (int kk = 0; kk < 4; kk++) {
            uint32_t ahi[4][4], alo[4][4], bhi[4][2], blo[4][2];
            const int arr = warp_m * 64 + (lane & 15);
            const int acb = kk * 32 + (lane >> 4) * 16;
#pragma unroll
            for (int mi = 0; mi < 4; mi++) {
                const int r = arr + mi * 16;
                const uint32_t ad = sb + swz(r, acb);
                LDSM4(ahi[mi][0], ahi[mi][1], ahi[mi][2], ahi[mi][3], ad + SA_HI);
                if (PASSES == 3)
                    LDSM4(alo[mi][0], alo[mi][1], alo[mi][2], alo[mi][3], ad + SA_LO);
            }
            const int br = warp_n * 32 + ((lane >> 4) << 3) + (lane & 7);
            const int bcb = kk * 32 + ((lane >> 3) & 1) * 16;
#pragma unroll
            for (int ni2 = 0; ni2 < 2; ni2++) {
                const int r = br + ni2 * 16;
                const uint32_t bd = sb + swz(r, bcb);
                LDSM4(bhi[ni2 * 2][0], bhi[ni2 * 2][1], bhi[ni2 * 2 + 1][0], bhi[ni2 * 2 + 1][1], bd + SB_HI);
                LDSM4(blo[ni2 * 2][0], blo[ni2 * 2][1], blo[ni2 * 2 + 1][0], blo[ni2 * 2 + 1][1], bd + SB_LO);
            }
#pragma unroll
            for (int mi = 0; mi < 4; mi++)
#pragma unroll
                for (int ni = 0; ni < 4; ni++)
                    MMA16816(acc[mi][ni], ahi[mi], bhi[ni]);
#pragma unroll
            for (int mi = 0; mi < 4; mi++)
#pragma unroll
                for (int ni = 0; ni < 4; ni++)
                    MMA16816(acc[mi][ni], ahi[mi], blo[ni]);
            if (PASSES == 3) {
#pragma unroll
                for (int mi = 0; mi < 4; mi++)
#pragma unroll
                    for (int ni = 0; ni < 4; ni++)
                        MMA16816(acc[mi][ni], alo[mi], bhi[ni]);
            }
        }
        if (s < 15) stsA((s + 1) & 1);
        __syncthreads();
    }

    // ---- epilogue via smem for coalesced stores ----
    float* ep = (float*)smem;
#pragma unroll
    for (int mi = 0; mi < 4; mi++) {
        const int r0 = warp_m * 64 + mi * 16 + (lane >> 2);
#pragma unroll
        for (int ni = 0; ni < 4; ni++) {
            const int c = warp_n * 32 + ni * 8 + 2 * (lane & 3);
            const float b0 = bias[n0 + c];
            const float b1 = bias[n0 + c + 1];
            if (MODE == 0) {
                ep[(c    ) * EPS + r0    ] = acc[mi][ni][0] + b0;
                ep[(c + 1) * EPS + r0    ] = acc[mi][ni][1] + b1;
                ep[(c    ) * EPS + r0 + 8] = acc[mi][ni][2] + b0;
                ep[(c + 1) * EPS + r0 + 8] = acc[mi][ni][3] + b1;
            } else {
                ep[(r0    ) * EPS + c    ] = acc[mi][ni][0] + b0;
                ep[(r0    ) * EPS + c + 1] = acc[mi][ni][1] + b1;
                ep[(r0 + 8) * EPS + c    ] = acc[mi][ni][2] + b0;
                ep[(r0 + 8) * EPS + c + 1] = acc[mi][ni][3] + b1;
            }
        }
    }
    __syncthreads();
#pragma unroll
    for (int j = 0; j < 16; j++) {
        const int row = j * 8 + wid;
        const float4 v = *(const float4*)(ep + row * EPS + lane * 4);
        if (MODE == 0)
            *(float4*)(C + ((size_t)(bb * DMODEL + n0 + row)) * LSEQ + l0 + lane * 4) = v;
        else
            *(float4*)(C + (size_t)(m0 + row) * DMODEL + n0 + lane * 4) = v;
    }
}

// ---------------------------------------------------------------------------
// Fused correlation kernel: radix-4 Stockham FFT + register-resident top-16
// ---------------------------------------------------------------------------
#define CORR_SMEM_BYTES (2 * LSEQ * 8 + LSEQ * 4 + 64 * 4)

__device__ __forceinline__ void fft4096(float2* buf0, float2* buf1, int tid)
{
    float2* src = buf0;
    float2* dst = buf1;
    int m = 1;
    for (int st = 0; st < 6; st++) {
        __syncthreads();
#pragma unroll
        for (int h = 0; h < 2; h++) {
            const int idx = tid + h * 512;
            const int k  = idx & (m - 1);
            const int Jm = idx - k;
            const float2 x0 = src[idx];
            const float2 x1 = src[idx + 1024];
            const float2 x2 = src[idx + 2048];
            const float2 x3 = src[idx + 3072];
            const float e0x = x0.x + x2.x, e0y = x0.y + x2.y;
            const float e1x = x0.x - x2.x, e1y = x0.y - x2.y;
            const float o0x = x1.x + x3.x, o0y = x1.y + x3.y;
            const float o1x = x1.x - x3.x, o1y = x1.y - x3.y;
            const float t3x = o1y, t3y = -o1x;
            const float ang = -1.5339807878856412e-3f * (float)Jm;
            float s1, c1;
            __sincosf(ang, &s1, &c1);
            const float c2 = c1 * c1 - s1 * s1, s2 = 2.0f * c1 * s1;
            const float c3 = c1 * c2 - s1 * s2, s3 = c1 * s2 + s1 * c2;
            const float u1x = e1x + t3x, u1y = e1y + t3y;
            const float u2x = e0x - o0x, u2y = e0y - o0y;
            const float u3x = e1x - t3x, u3y = e1y - t3y;
            const int base = idx + 3 * Jm;
            dst[base]         = make_float2(e0x + o0x, e0y + o0y);
            dst[base + m]     = make_float2(c1 * u1x - s1 * u1y, c1 * u1y + s1 * u1x);
            dst[base + 2 * m] = make_float2(c2 * u2x - s2 * u2y, c2 * u2y + s2 * u2x);
            dst[base + 3 * m] = make_float2(c3 * u3x - s3 * u3y, c3 * u3y + s3 * u3x);
        }
        float2* t = src; src = dst; dst = t;
        m <<= 2;
    }
    __syncthreads();
}

__global__ void __launch_bounds__(512, 1) corr_kernel(
    const float* __restrict__ qT, const float* __restrict__ kT,
    const float* __restrict__ vT, __half* __restrict__ aHi)
{
    float* smem = (float*)smem_raw;
    float2* Az   = (float2*)smem;
    float2* Bz   = Az + LSEQ;
    float*  vbuf = (float*)(Bz + LSEQ);
    float*  rval = vbuf + LSEQ;
    int*    ridx = (int*)(rval + 16);
    float*  wts  = (float*)(ridx + 16);
    int*    dly  = (int*)(wts + 16);

    const int tid = threadIdx.x;
    const size_t row = blockIdx.x;
    const float* qp = qT + row * LSEQ;
    const float* kp = kT + row * LSEQ;
    const float* vp = vT + row * LSEQ;

#pragma unroll
    for (int i4 = tid; i4 < LSEQ / 4; i4 += 512) {
        const float4 q4 = ((const float4*)qp)[i4];
        const float4 k4 = ((const float4*)kp)[i4];
        const float4 v4 = ((const float4*)vp)[i4];
        Az[i4 * 4 + 0] = make_float2(q4.x, k4.x);
        Az[i4 * 4 + 1] = make_float2(q4.y, k4.y);
        Az[i4 * 4 + 2] = make_float2(q4.z, k4.z);
        Az[i4 * 4 + 3] = make_float2(q4.w, k4.w);
        *(float4*)(vbuf + i4 * 4) = v4;
    }

    fft4096(Az, Bz, tid);

    for (int f = tid; f < LSEQ; f += 512) {
        const float2 zf = Az[f];
        const float2 zc = Az[(LSEQ - f) & (LSEQ - 1)];
        const float qx = 0.5f * (zf.x + zc.x);
        const float qy = 0.5f * (zf.y - zc.y);
        const float dx = 0.5f * (zf.x - zc.x);
        const float dy = 0.5f * (zf.y + zc.y);
        const float kx = dy;
        const float ky = -dx;
        const float sx = qx * kx + qy * ky;
        const float sy = qy * kx - qx * ky;
        Bz[f] = make_float2(sx, -sy);
    }

    fft4096(Bz, Az, tid);

    // ---- register-resident top-16 ----
    const int lane = tid & 31;
    const int wrp  = tid >> 5;
    float cv[8];
#pragma unroll
    for (int c = 0; c < 8; c++) cv[c] = Bz[tid + 512 * c].x;

    for (int it = 0; it < TOPK; it++) {
        float best = cv[0];
        int   bc   = 0;
#pragma unroll
        for (int c = 1; c < 8; c++)
            if (cv[c] > best) { best = cv[c]; bc = c; }
        int bi = tid + 512 * bc;
#pragma unroll
        for (int off = 16; off; off >>= 1) {
            const float ov = __shfl_down_sync(0xffffffffu, best, off);
            const int   oi = __shfl_down_sync(0xffffffffu, bi, off);
            if (ov > best || (ov == best && oi < bi)) { best = ov; bi = oi; }
        }
        if (lane == 0) { rval[wrp] = best; ridx[wrp] = bi; }
        __syncthreads();
        if (tid < 32) {
            float v = (lane < 16) ? rval[lane] : -INFINITY;
            int   i = (lane < 16) ? ridx[lane] : LSEQ;
#pragma unroll
            for (int off = 8; off; off >>= 1) {
                const float ov = __shfl_down_sync(0xffffffffu, v, off);
                const int   oi = __shfl_down_sync(0xffffffffu, i, off);
                if (ov > v || (ov == v && oi < i)) { v = ov; i = oi; }
            }
            if (lane == 0) { wts[it] = v * (1.0f / (float)LSEQ); dly[it] = i; }
        }
        __syncthreads();
        const int gi = dly[it];
        if (tid == (gi & 511)) cv[gi >> 9] = -INFINITY;
    }

    if (tid == 0) {
        float mx = wts[0];
        for (int i = 1; i < TOPK; i++) mx = fmaxf(mx, wts[i]);
        float s = 0.0f;
        for (int i = 0; i < TOPK; i++) { const float e = expf(wts[i] - mx); wts[i] = e; s += e; }
        const float inv = 1.0f / s;
        for (int i = 0; i < TOPK; i++) wts[i] *= inv;
    }
    __syncthreads();

    float w[TOPK];
    int   d[TOPK];
#pragma unroll
    for (int i = 0; i < TOPK; i++) { w[i] = wts[i]; d[i] = dly[i]; }

    __half* oh = aHi + row * LSEQ;
    for (int t = tid; t < LSEQ; t += 512) {
        float acc = 0.0f;
#pragma unroll
        for (int i = 0; i < TOPK; i++)
            acc += w[i] * vbuf[(t + d[i]) & (LSEQ - 1)];
        oh[t] = __float2half_rn(acc);
    }
}

// ---------------------------------------------------------------------------
// Launch
// ---------------------------------------------------------------------------
extern "C" void kernel_launch(void* const* d_in, const int* in_sizes, int n_in,
                              void* d_out, int out_size)
{
    const float* q  = (const float*)d_in[0];
    const float* k  = (const float*)d_in[1];
    const float* v  = (const float*)d_in[2];
    const float* Wq = (const float*)d_in[3];
    const float* bq = (const float*)d_in[4];
    const float* Wk = (const float*)d_in[5];
    const float* bk = (const float*)d_in[6];
    const float* Wv = (const float*)d_in[7];
    const float* bv = (const float*)d_in[8];
    const float* Wo = (const float*)d_in[9];
    const float* bo = (const float*)d_in[10];
    float* out = (float*)d_out;

    float  *qT, *kT, *vT;
    __half *ahi, *wthi, *wtlo;
    cudaGetSymbolAddress((void**)&qT,   g_qT);
    cudaGetSymbolAddress((void**)&kT,   g_kT);
    cudaGetSymbolAddress((void**)&vT,   g_vT);
    cudaGetSymbolAddress((void**)&ahi,  g_a_hi);
    cudaGetSymbolAddress((void**)&wthi, g_wt_hi);
    cudaGetSymbolAddress((void**)&wtlo, g_wt_lo);

    cudaFuncSetAttribute(hgemm_kernel<0,3>, cudaFuncAttributeMaxDynamicSharedMemorySize, GEMM_SMEM);
    cudaFuncSetAttribute(hgemm_kernel<0,2>, cudaFuncAttributeMaxDynamicSharedMemorySize, GEMM_SMEM);
    cudaFuncSetAttribute(hgemm_kernel<1,2>, cudaFuncAttributeMaxDynamicSharedMemorySize, GEMM_SMEM);
    cudaFuncSetAttribute(corr_kernel,       cudaFuncAttributeMaxDynamicSharedMemorySize, CORR_SMEM_BYTES);

    const int WSZ = DMODEL * DMODEL;
    const dim3 wgrid(32, 32);
    wsplit_kernel<<<wgrid, 256>>>(Wq, wthi + 0 * WSZ, wtlo + 0 * WSZ);
    wsplit_kernel<<<wgrid, 256>>>(Wk, wthi + 1 * WSZ, wtlo + 1 * WSZ);
    wsplit_kernel<<<wgrid, 256>>>(Wv, wthi + 2 * WSZ, wtlo + 2 * WSZ);
    wsplit_kernel<<<wgrid, 256>>>(Wo, wthi + 3 * WSZ, wtlo + 3 * WSZ);

    const dim3 gg(DMODEL / 128, MTOT / 128);   // (8, 256)

    hgemm_kernel<0,3><<<gg, 256, GEMM_SMEM>>>(q, wthi + 0 * WSZ, wtlo + 0 * WSZ, bq, qT);
    hgemm_kernel<0,3><<<gg, 256, GEMM_SMEM>>>(k, wthi + 1 * WSZ, wtlo + 1 * WSZ, bk, kT);
    hgemm_kernel<0,2><<<gg, 256, GEMM_SMEM>>>(v, wthi + 2 * WSZ, wtlo + 2 * WSZ, bv, vT);

    corr_kernel<<<NROWS, 512, CORR_SMEM_BYTES>>>(qT, kT, vT, ahi);

    hgemm_kernel<1,2><<<gg, 256, GEMM_SMEM>>>(ahi, wthi + 3 * WSZ, wtlo + 3 * WSZ, bo, out);
}

// round 8
// speedup vs baseline: 2.6639x; 1.0049x over previous
#include <cuda_runtime.h>
#include <cuda_fp16.h>
#include <math.h>
#include <stdint.h>

#define NB      8
#define LSEQ    4096
#define DMODEL  1024
#define TOPK    16
#define NROWS   (NB * DMODEL)          // 8192
#define MTOT    (NB * LSEQ)            // 32768

// ---------------------------------------------------------------------------
// Scratch (device globals; no runtime allocation allowed)
// ---------------------------------------------------------------------------
__device__ float  g_qT[(size_t)NROWS * LSEQ];   // [b*1024 + hd][l] fp32
__device__ float  g_kT[(size_t)NROWS * LSEQ];
__device__ float  g_vT[(size_t)NROWS * LSEQ];
__device__ __half g_a_hi[(size_t)MTOT * DMODEL];   // agg, batched [(b*1024+hd)*4096+l]
__device__ __half g_wt_hi[4 * DMODEL * DMODEL];    // W^T, [n,k], 4 matrices
__device__ __half g_wt_lo[4 * DMODEL * DMODEL];

extern __shared__ char smem_raw[];

// ---------------------------------------------------------------------------
// PTX helpers (baseline sm_80+: cp.async / ldmatrix / mma)
// ---------------------------------------------------------------------------
__device__ __forceinline__ uint32_t smem_u32(const void* p) {
    uint32_t a;
    asm("{ .reg .u64 t; cvta.to.shared.u64 t, %1; cvt.u32.u64 %0, t; }" : "=r"(a) : "l"(p));
    return a;
}
__device__ __forceinline__ void cpa16(uint32_t d, const void* g) {
    asm volatile("cp.async.cg.shared.global [%0], [%1], 16;" :: "r"(d), "l"(g));
}
#define CPA_COMMIT() asm volatile("cp.async.commit_group;" ::: "memory")
#define CPA_WAIT(n)  asm volatile("cp.async.wait_group %0;" :: "n"(n) : "memory")

#define LDSM4(r0, r1, r2, r3, a) \
    asm volatile("ldmatrix.sync.aligned.m8n8.x4.shared.b16 {%0,%1,%2,%3}, [%4];" \
        : "=r"(r0), "=r"(r1), "=r"(r2), "=r"(r3) : "r"(a))

#define MMA16816(d, a, b) \
    asm volatile("mma.sync.aligned.m16n8k16.row.col.f32.f16.f16.f32 " \
        "{%0,%1,%2,%3}, {%4,%5,%6,%7}, {%8,%9}, {%0,%1,%2,%3};" \
        : "+f"((d)[0]), "+f"((d)[1]), "+f"((d)[2]), "+f"((d)[3]) \
        : "r"((a)[0]), "r"((a)[1]), "r"((a)[2]), "r"((a)[3]), "r"((b)[0]), "r"((b)[1]))

// pack two halves into u32
__device__ __forceinline__ uint32_t halves2u32(__half a, __half b) {
    __half2 h = __halves2half2(a, b);
    return *(uint32_t*)&h;
}
__device__ __forceinline__ float2 cmul(float2 a, float2 b) {
    return make_float2(a.x * b.x - a.y * b.y, a.x * b.y + a.y * b.x);
}

// ---------------------------------------------------------------------------
// Batched W [k,n] -> W^T [n,k] hi/lo split (blockIdx.z selects matrix)
// ---------------------------------------------------------------------------
__global__ void __launch_bounds__(256) wsplit_kernel(
    const float* __restrict__ W0, const float* __restrict__ W1,
    const float* __restrict__ W2, const float* __restrict__ W3,
    __half* __restrict__ Thi, __half* __restrict__ Tlo)
{
    const float* W = (blockIdx.z == 0) ? W0 : (blockIdx.z == 1) ? W1
                   : (blockIdx.z == 2) ? W2 : W3;
    __half* hi = Thi + (size_t)blockIdx.z * DMODEL * DMODEL;
    __half* lo = Tlo + (size_t)blockIdx.z * DMODEL * DMODEL;

    __shared__ float t[32][33];
    const int bx = blockIdx.x * 32;   // n block
    const int by = blockIdx.y * 32;   // k block
    const int tx = threadIdx.x & 31;
    const int ty = threadIdx.x >> 5;  // 0..7
#pragma unroll
    for (int j = 0; j < 4; j++)
        t[ty + j * 8][tx] = W[(size_t)(by + ty + j * 8) * DMODEL + bx + tx];
    __syncthreads();
#pragma unroll
    for (int j = 0; j < 4; j++) {
        const float v = t[tx][ty + j * 8];
        const __half h = __float2half_rn(v);
        const size_t o = (size_t)(bx + ty + j * 8) * DMODEL + by + tx;
        hi[o] = h;
        lo[o] = __float2half_rn(v - __half2float(h));
    }
}

// ---------------------------------------------------------------------------
// Split-fp16 HMMA GEMM with fused on-the-fly A split (unchanged from R7 pass)
// ---------------------------------------------------------------------------
#define SA_HI 0
#define SA_LO 16384
#define SB_HI 32768
#define SB_LO 49152
#define STAGE 65536
#define GEMM_SMEM 131072
#define EPS 132

__device__ __forceinline__ int swz(int r, int cb) {
    return r * 128 + (cb ^ ((r & 7) << 4));
}

template<int MODE, int PASSES>
__global__ void __launch_bounds__(256, 1) hgemm_kernel(
    const void* __restrict__ Ain,
    const __half* __restrict__ Bhi, const __half* __restrict__ Blo,
    const float* __restrict__ bias, float* __restrict__ C)
{
    char* smem = smem_raw;
    const int tid  = threadIdx.x;
    const int wid  = tid >> 5;
    const int lane = tid & 31;
    const int n0 = blockIdx.x * 128;
    const int m0 = blockIdx.y * 128;
    const int warp_m = wid & 1;
    const int warp_n = wid >> 1;
    const int bb = m0 >> 12;
    const int l0 = m0 & (LSEQ - 1);
    const uint32_t sbase = smem_u32(smem);

    const float*  Af = (const float*)Ain;    // MODE 0
    const __half* Ah = (const __half*)Ain;   // MODE 1

    float acc[4][4][4];
#pragma unroll
    for (int mi = 0; mi < 4; mi++)
#pragma unroll
        for (int ni = 0; ni < 4; ni++)
#pragma unroll
            for (int j = 0; j < 4; j++) acc[mi][ni][j] = 0.0f;

    float4 ar[8];
    float4 ar1[4];

    auto loadB = [&](int st, int kt) {
        const uint32_t sb = sbase + st * STAGE;
#pragma unroll
        for (int i = 0; i < 4; i++) {
            const int idx = tid + i * 256;
            const int r = idx >> 3, ch = idx & 7;
            const int sw = swz(r, ch * 16);
            const size_t go = (size_t)(n0 + r) * DMODEL + kt + ch * 8;
            cpa16(sb + SB_HI + sw, Bhi + go);
            cpa16(sb + SB_LO + sw, Blo + go);
        }
        CPA_COMMIT();
    };

    auto ldgA = [&](int kt) {
        if (MODE == 0) {
#pragma unroll
            for (int j = 0; j < 8; j++) {
                const int c = tid + j * 256;
                const int r = c >> 4, c4 = c & 15;
                ar[j] = *(const float4*)(Af + (size_t)(m0 + r) * DMODEL + kt + c4 * 4);
            }
        } else {
#pragma unroll
            for (int j = 0; j < 4; j++) {
                const int idx = tid + j * 256;
                const int k  = idx & 63;
                const int m  = (idx >> 6) * 8;
                ar1[j] = *(const float4*)(Ah + ((size_t)(bb * DMODEL + kt + k)) * LSEQ + l0 + m);
            }
        }
    };

    auto stsA = [&](int st) {
        char* buf = smem + st * STAGE;
        if (MODE == 0) {
#pragma unroll
            for (int j = 0; j < 8; j++) {
                const int c = tid + j * 256;
                const int r = c >> 4, c4 = c & 15;
                const float4 v = ar[j];
                const __half h0 = __float2half_rn(v.x);
                const __half h1 = __float2half_rn(v.y);
                const __half h2 = __float2half_rn(v.z);
                const __half h3 = __float2half_rn(v.w);
                const int o8 = r * 128 + ((c4 * 8) ^ ((r & 7) << 4));
                uint2 hh;
                hh.x = halves2u32(h0, h1);
                hh.y = halves2u32(h2, h3);
                *(uint2*)(buf + SA_HI + o8) = hh;
                if (PASSES == 3) {
                    uint2 ll;
                    ll.x = halves2u32(__float2half_rn(v.x - __half2float(h0)),
                                      __float2half_rn(v.y - __half2float(h1)));
                    ll.y = halves2u32(__float2half_rn(v.z - __half2float(h2)),
                                      __float2half_rn(v.w - __half2float(h3)));
                    *(uint2*)(buf + SA_LO + o8) = ll;
                }
            }
        } else {
#pragma unroll
            for (int j = 0; j < 4; j++) {
                const int idx = tid + j * 256;
                const int k  = idx & 63;
                const int m  = (idx >> 6) * 8;
                const __half* hh = (const __half*)&ar1[j];
#pragma unroll
                for (int q = 0; q < 8; q++)
                    *(__half*)(buf + SA_HI + swz(m + q, k * 2)) = hh[q];
            }
        }
    };

    loadB(0, 0);
    ldgA(0);
    stsA(0);

    for (int s = 0; s < 16; s++) {
        if (s < 15) { loadB((s + 1) & 1, (s + 1) * 64); ldgA((s + 1) * 64); }
        if (s < 15) { CPA_WAIT(1); } else { CPA_WAIT(0); }
        __syncthreads();

        const uint32_t sb = sbase + (s & 1) * STAGE;
#pragma unroll
        for (int kk = 0; kk < 4; kk++) {
            uint32_t ahi[4][4], alo[4][4], bhi[4][2], blo[4][2];
            const int arr = warp_m * 64 + (lane & 15);
            const int acb = kk * 32 + (lane >> 4) * 16;
#pragma unroll
            for (int mi = 0; mi < 4; mi++) {
                const int r = arr + mi * 16;
                const uint32_t ad = sb + swz(r, acb);
                LDSM4(ahi[mi][0], ahi[mi][1], ahi[mi][2], ahi[mi][3], ad + SA_HI);
                if (PASSES == 3)
                    LDSM4(alo[mi][0], alo[mi][1], alo[mi][2], alo[mi][3], ad + SA_LO);
            }
            const int br = warp_n * 32 + ((lane >> 4) << 3) + (lane & 7);
            const int bcb = kk * 32 + ((lane >> 3) & 1) * 16;
#pragma unroll
            for (int ni2 = 0; ni2 < 2; ni2++) {
                const int r = br + ni2 * 16;
                const uint32_t bd = sb + swz(r, bcb);
                LDSM4(bhi[ni2 * 2][0], bhi[ni2 * 2][1], bhi[ni2 * 2 + 1][0], bhi[ni2 * 2 + 1][1], bd + SB_HI);
                LDSM4(blo[ni2 * 2][0], blo[ni2 * 2][1], blo[ni2 * 2 + 1][0], blo[ni2 * 2 + 1][1], bd + SB_LO);
            }
#pragma unroll
            for (int mi = 0; mi < 4; mi++)
#pragma unroll
                for (int ni = 0; ni < 4; ni++)
                    MMA16816(acc[mi][ni], ahi[mi], bhi[ni]);
#pragma unroll
            for (int mi = 0; mi < 4; mi++)
#pragma unroll
                for (int ni = 0; ni < 4; ni++)
                    MMA16816(acc[mi][ni], ahi[mi], blo[ni]);
            if (PASSES == 3) {
#pragma unroll
                for (int mi = 0; mi < 4; mi++)
#pragma unroll
                    for (int ni = 0; ni < 4; ni++)
                        MMA16816(acc[mi][ni], alo[mi], bhi[ni]);
            }
        }
        if (s < 15) stsA((s + 1) & 1);
        __syncthreads();
    }

    float* ep = (float*)smem;
#pragma unroll
    for (int mi = 0; mi < 4; mi++) {
        const int r0 = warp_m * 64 + mi * 16 + (lane >> 2);
#pragma unroll
        for (int ni = 0; ni < 4; ni++) {
            const int c = warp_n * 32 + ni * 8 + 2 * (lane & 3);
            const float b0 = bias[n0 + c];
            const float b1 = bias[n0 + c + 1];
            if (MODE == 0) {
                ep[(c    ) * EPS + r0    ] = acc[mi][ni][0] + b0;
                ep[(c + 1) * EPS + r0    ] = acc[mi][ni][1] + b1;
                ep[(c    ) * EPS + r0 + 8] = acc[mi][ni][2] + b0;
                ep[(c + 1) * EPS + r0 + 8] = acc[mi][ni][3] + b1;
            } else {
                ep[(r0    ) * EPS + c    ] = acc[mi][ni][0] + b0;
                ep[(r0    ) * EPS + c + 1] = acc[mi][ni][1] + b1;
                ep[(r0 + 8) * EPS + c    ] = acc[mi][ni][2] + b0;
                ep[(r0 + 8) * EPS + c + 1] = acc[mi][ni][3] + b1;
            }
        }
    }
    __syncthreads();
#pragma unroll
    for (int j = 0; j < 16; j++) {
        const int row = j * 8 + wid;
        const float4 v = *(const float4*)(ep + row * EPS + lane * 4);
        if (MODE == 0)
            *(float4*)(C + ((size_t)(bb * DMODEL + n0 + row)) * LSEQ + l0 + lane * 4) = v;
        else
            *(float4*)(C + (size_t)(m0 + row) * DMODEL + n0 + lane * 4) = v;
    }
}

// ---------------------------------------------------------------------------
// Fused correlation kernel: radix-8 Stockham FFT (4 stages) + reg top-16
// ---------------------------------------------------------------------------
#define CORR_SMEM_BYTES (2 * LSEQ * 8 + LSEQ * 4 + 64 * 4)

__device__ __forceinline__ void fft4096(float2* buf0, float2* buf1, int tid)
{
    // 4 radix-8 Stockham stages (4096 = 8^4); result ends back in buf0.
    const float C707 = 0.70710678118654752f;
    float2* src = buf0;
    float2* dst = buf1;
    int m = 1;
    for (int st = 0; st < 4; st++) {
        __syncthreads();
        const int k  = tid & (m - 1);
        const int Jm = tid - k;
        const float2 x0 = src[tid];
        const float2 x1 = src[tid + 512];
        const float2 x2 = src[tid + 1024];
        const float2 x3 = src[tid + 1536];
        const float2 x4 = src[tid + 2048];
        const float2 x5 = src[tid + 2560];
        const float2 x6 = src[tid + 3072];
        const float2 x7 = src[tid + 3584];
        // even radix-4 (x0,x2,x4,x6), w4 = -i
        const float a0x = x0.x + x4.x, a0y = x0.y + x4.y;
        const float a1x = x0.x - x4.x, a1y = x0.y - x4.y;
        const float b0x = x2.x + x6.x, b0y = x2.y + x6.y;
        const float b1x = x2.x - x6.x, b1y = x2.y - x6.y;
        const float E0x = a0x + b0x, E0y = a0y + b0y;
        const float E1x = a1x + b1y, E1y = a1y - b1x;
        const float E2x = a0x - b0x, E2y = a0y - b0y;
        const float E3x = a1x - b1y, E3y = a1y + b1x;
        // odd radix-4 (x1,x3,x5,x7)
        const float c0x = x1.x + x5.x, c0y = x1.y + x5.y;
        const float c1x = x1.x - x5.x, c1y = x1.y - x5.y;
        const float d0x = x3.x + x7.x, d0y = x3.y + x7.y;
        const float d1x = x3.x - x7.x, d1y = x3.y - x7.y;
        const float O0x = c0x + d0x, O0y = c0y + d0y;
        const float O1x = c1x + d1y, O1y = c1y - d1x;
        const float O2x = c0x - d0x, O2y = c0y - d0y;
        const float O3x = c1x - d1y, O3y = c1y + d1x;
        // t_p = w8^p * O_p  (w8 = (c,-c), w8^2 = -i, w8^3 = (-c,-c))
        const float t1x = C707 * (O1x + O1y), t1y = C707 * (O1y - O1x);
        const float t2x = O2y,               t2y = -O2x;
        const float t3x = C707 * (O3y - O3x), t3y = -C707 * (O3x + O3y);
        const float2 y0 = make_float2(E0x + O0x, E0y + O0y);
        const float2 y4 = make_float2(E0x - O0x, E0y - O0y);
        const float2 y1 = make_float2(E1x + t1x, E1y + t1y);
        const float2 y5 = make_float2(E1x - t1x, E1y - t1y);
        const float2 y2 = make_float2(E2x + t2x, E2y + t2y);
        const float2 y6 = make_float2(E2x - t2x, E2y - t2y);
        const float2 y3 = make_float2(E3x + t3x, E3y + t3y);
        const float2 y7 = make_float2(E3x - t3x, E3y - t3y);
        // twiddles w^p, w = exp(-2*pi*i*Jm/4096)
        const float ang = -1.5339807878856412e-3f * (float)Jm;
        float s1, cc1;
        __sincosf(ang, &s1, &cc1);
        const float2 w1 = make_float2(cc1, s1);
        const float2 w2 = cmul(w1, w1);
        const float2 w3 = cmul(w2, w1);
        const float2 w4 = cmul(w2, w2);
        const float2 w5 = cmul(w3, w2);
        const float2 w6 = cmul(w3, w3);
        const float2 w7 = cmul(w4, w3);
        const int base = 8 * Jm + k;
        dst[base]         = y0;
        dst[base + m]     = cmul(y1, w1);
        dst[base + 2 * m] = cmul(y2, w2);
        dst[base + 3 * m] = cmul(y3, w3);
        dst[base + 4 * m] = cmul(y4, w4);
        dst[base + 5 * m] = cmul(y5, w5);
        dst[base + 6 * m] = cmul(y6, w6);
        dst[base + 7 * m] = cmul(y7, w7);
        float2* t = src; src = dst; dst = t;
        m <<= 3;
    }
    __syncthreads();
}

__global__ void __launch_bounds__(512, 1) corr_kernel(
    const float* __restrict__ qT, const float* __restrict__ kT,
    const float* __restrict__ vT, __half* __restrict__ aHi)
{
    float* smem = (float*)smem_raw;
    float2* Az   = (float2*)smem;
    float2* Bz   = Az + LSEQ;
    float*  vbuf = (float*)(Bz + LSEQ);
    float*  rval = vbuf + LSEQ;
    int*    ridx = (int*)(rval + 16);
    float*  wts  = (float*)(ridx + 16);
    int*    dly  = (int*)(wts + 16);

    const int tid = threadIdx.x;
    const size_t row = blockIdx.x;
    const float* qp = qT + row * LSEQ;
    const float* kp = kT + row * LSEQ;
    const float* vp = vT + row * LSEQ;

#pragma unroll
    for (int i4 = tid; i4 < LSEQ / 4; i4 += 512) {
        const float4 q4 = ((const float4*)qp)[i4];
        const float4 k4 = ((const float4*)kp)[i4];
        const float4 v4 = ((const float4*)vp)[i4];
        Az[i4 * 4 + 0] = make_float2(q4.x, k4.x);
        Az[i4 * 4 + 1] = make_float2(q4.y, k4.y);
        Az[i4 * 4 + 2] = make_float2(q4.z, k4.z);
        Az[i4 * 4 + 3] = make_float2(q4.w, k4.w);
        *(float4*)(vbuf + i4 * 4) = v4;
    }

    fft4096(Az, Bz, tid);

    for (int f = tid; f < LSEQ; f += 512) {
        const float2 zf = Az[f];
        const float2 zc = Az[(LSEQ - f) & (LSEQ - 1)];
        const float qx = 0.5f * (zf.x + zc.x);
        const float qy = 0.5f * (zf.y - zc.y);
        const float dx = 0.5f * (zf.x - zc.x);
        const float dy = 0.5f * (zf.y + zc.y);
        const float kx = dy;
        const float ky = -dx;
        const float sx = qx * kx + qy * ky;
        const float sy = qy * kx - qx * ky;
        Bz[f] = make_float2(sx, -sy);
    }

    fft4096(Bz, Az, tid);

    // ---- register-resident top-16 ----
    const int lane = tid & 31;
    const int wrp  = tid >> 5;
    float cv[8];
#pragma unroll
    for (int c = 0; c < 8; c++) cv[c] = Bz[tid + 512 * c].x;

    for (int it = 0; it < TOPK; it++) {
        float best = cv[0];
        int   bc   = 0;
#pragma unroll
        for (int c = 1; c < 8; c++)
            if (cv[c] > best) { best = cv[c]; bc = c; }
        int bi = tid + 512 * bc;
#pragma unroll
        for (int off = 16; off; off >>= 1) {
            const float ov = __shfl_down_sync(0xffffffffu, best, off);
            const int   oi = __shfl_down_sync(0xffffffffu, bi, off);
            if (ov > best || (ov == best && oi < bi)) { best = ov; bi = oi; }
        }
        if (lane == 0) { rval[wrp] = best; ridx[wrp] = bi; }
        __syncthreads();
        if (tid < 32) {
            float v = (lane < 16) ? rval[lane] : -INFINITY;
            int   i = (lane < 16) ? ridx[lane] : LSEQ;
#pragma unroll
            for (int off = 8; off; off >>= 1) {
                const float ov = __shfl_down_sync(0xffffffffu, v, off);
                const int   oi = __shfl_down_sync(0xffffffffu, i, off);
                if (ov > v || (ov == v && oi < i)) { v = ov; i = oi; }
            }
            if (lane == 0) { wts[it] = v * (1.0f / (float)LSEQ); dly[it] = i; }
        }
        __syncthreads();
        const int gi = dly[it];
        if (tid == (gi & 511)) cv[gi >> 9] = -INFINITY;
    }

    if (tid == 0) {
        float mx = wts[0];
        for (int i = 1; i < TOPK; i++) mx = fmaxf(mx, wts[i]);
        float s = 0.0f;
        for (int i = 0; i < TOPK; i++) { const float e = expf(wts[i] - mx); wts[i] = e; s += e; }
        const float inv = 1.0f / s;
        for (int i = 0; i < TOPK; i++) wts[i] *= inv;
    }
    __syncthreads();

    float w[TOPK];
    int   d[TOPK];
#pragma unroll
    for (int i = 0; i < TOPK; i++) { w[i] = wts[i]; d[i] = dly[i]; }

    __half* oh = aHi + row * LSEQ;
    for (int t = tid; t < LSEQ; t += 512) {
        float acc = 0.0f;
#pragma unroll
        for (int i = 0; i < TOPK; i++)
            acc += w[i] * vbuf[(t + d[i]) & (LSEQ - 1)];
        oh[t] = __float2half_rn(acc);
    }
}

// ---------------------------------------------------------------------------
// Launch
// ---------------------------------------------------------------------------
extern "C" void kernel_launch(void* const* d_in, const int* in_sizes, int n_in,
                              void* d_out, int out_size)
{
    const float* q  = (const float*)d_in[0];
    const float* k  = (const float*)d_in[1];
    const float* v  = (const float*)d_in[2];
    const float* Wq = (const float*)d_in[3];
    const float* bq = (const float*)d_in[4];
    const float* Wk = (const float*)d_in[5];
    const float* bk = (const float*)d_in[6];
    const float* Wv = (const float*)d_in[7];
    const float* bv = (const float*)d_in[8];
    const float* Wo = (const float*)d_in[9];
    const float* bo = (const float*)d_in[10];
    float* out = (float*)d_out;

    float  *qT, *kT, *vT;
    __half *ahi, *wthi, *wtlo;
    cudaGetSymbolAddress((void**)&qT,   g_qT);
    cudaGetSymbolAddress((void**)&kT,   g_kT);
    cudaGetSymbolAddress((void**)&vT,   g_vT);
    cudaGetSymbolAddress((void**)&ahi,  g_a_hi);
    cudaGetSymbolAddress((void**)&wthi, g_wt_hi);
    cudaGetSymbolAddress((void**)&wtlo, g_wt_lo);

    cudaFuncSetAttribute(hgemm_kernel<0,3>, cudaFuncAttributeMaxDynamicSharedMemorySize, GEMM_SMEM);
    cudaFuncSetAttribute(hgemm_kernel<0,2>, cudaFuncAttributeMaxDynamicSharedMemorySize, GEMM_SMEM);
    cudaFuncSetAttribute(hgemm_kernel<1,2>, cudaFuncAttributeMaxDynamicSharedMemorySize, GEMM_SMEM);
    cudaFuncSetAttribute(corr_kernel,       cudaFuncAttributeMaxDynamicSharedMemorySize, CORR_SMEM_BYTES);

    const int WSZ = DMODEL * DMODEL;
    wsplit_kernel<<<dim3(32, 32, 4), 256>>>(Wq, Wk, Wv, Wo, wthi, wtlo);

    const dim3 gg(DMODEL / 128, MTOT / 128);   // (8, 256)

    hgemm_kernel<0,3><<<gg, 256, GEMM_SMEM>>>(q, wthi + 0 * WSZ, wtlo + 0 * WSZ, bq, qT);
    hgemm_kernel<0,3><<<gg, 256, GEMM_SMEM>>>(k, wthi + 1 * WSZ, wtlo + 1 * WSZ, bk, kT);
    hgemm_kernel<0,2><<<gg, 256, GEMM_SMEM>>>(v, wthi + 2 * WSZ, wtlo + 2 * WSZ, bv, vT);

    corr_kernel<<<NROWS, 512, CORR_SMEM_BYTES>>>(qT, kT, vT, ahi);

    hgemm_kernel<1,2><<<gg, 256, GEMM_SMEM>>>(ahi, wthi + 3 * WSZ, wtlo + 3 * WSZ, bo, out);
}